// round 6
// baseline (speedup 1.0000x reference)
#include <cuda_runtime.h>
#include <cuda_fp16.h>
#include <math.h>

#define MAXN 50000
#define MAXE 800000
#define MAXEP (MAXN + MAXE)

// ---------------- scratch (device globals; no allocation allowed) ----------------
__device__ float g_xl1[MAXN * 128];
__device__ float g_xr1[MAXN * 128];
__device__ uint2 g_xl1h[MAXN * 32];    // half2 x2 per uint2: 128 ch = 32 uint2/row
__device__ float g_res[MAXN * 32];
__device__ float g_agg1[MAXN * 128];   // normalized conv1 output (pre-bias)
__device__ float g_xl2[MAXN * 32];
__device__ __half g_xl2h[MAXN * 32];
__device__ float g_xr2[MAXN * 32];
__device__ float g_agg2[MAXN * 32];    // normalized conv2 output (pre-bias)
__device__ double g_sum1[128], g_sq1[128];
__device__ double g_sum2[32], g_sq2[32];
__device__ float g_scale1[128], g_shift1[128];
__device__ float g_scale2[32], g_shift2[32];
// CSR-by-destination
__device__ int g_count[MAXN];
__device__ int g_off[MAXN + 1];
__device__ int g_cursor[MAXN];
__device__ int g_bsum[128];
__device__ int g_csr[MAXEP];

// ---------------- CSR build ----------------
__global__ void csr_init(int N) {
    int i = blockIdx.x * blockDim.x + threadIdx.x;
    if (i < N) g_count[i] = 1;   // self-loop
}

__global__ void csr_hist(const int* __restrict__ ei, int E) {
    int e = blockIdx.x * blockDim.x + threadIdx.x;
    if (e < E) atomicAdd(&g_count[ei[E + e]], 1);
}

__global__ void csr_scan1(int N) {
    __shared__ int sh[512];
    int tid = threadIdx.x;
    int i = blockIdx.x * 512 + tid;
    int v = (i < N) ? g_count[i] : 0;
    sh[tid] = v;
    __syncthreads();
    for (int ofs = 1; ofs < 512; ofs <<= 1) {
        int t = (tid >= ofs) ? sh[tid - ofs] : 0;
        __syncthreads();
        sh[tid] += t;
        __syncthreads();
    }
    if (i < N) g_off[i] = sh[tid] - v;
    if (tid == 511) g_bsum[blockIdx.x] = sh[511];
}

__global__ void csr_scan2(int nb) {
    __shared__ int sh[128];
    int tid = threadIdx.x;
    int v = (tid < nb) ? g_bsum[tid] : 0;
    sh[tid] = v;
    __syncthreads();
    for (int ofs = 1; ofs < 128; ofs <<= 1) {
        int t = (tid >= ofs) ? sh[tid - ofs] : 0;
        __syncthreads();
        sh[tid] += t;
        __syncthreads();
    }
    if (tid < nb) g_bsum[tid] = sh[tid] - v;
}

__global__ void csr_scan3(int N, int EP) {
    int i = blockIdx.x * blockDim.x + threadIdx.x;
    if (i < N) {
        int o = g_off[i] + g_bsum[i >> 9];
        g_off[i] = o;
        g_cursor[i] = o;
    }
    if (i == 0) g_off[N] = EP;
}

__global__ void csr_scatter(const int* __restrict__ ei, int E, int N) {
    int e = blockIdx.x * blockDim.x + threadIdx.x;
    int EP = E + N;
    if (e >= EP) return;
    int s, d;
    if (e < E) { s = ei[e]; d = ei[E + e]; }
    else { s = e - E; d = s; }
    int pos = atomicAdd(&g_cursor[d], 1);
    g_csr[pos] = s;
}

// ---------------- half conversions ----------------
__global__ void to_half1(int total)   // total = N*32 uint2 slots
{
    int i = blockIdx.x * blockDim.x + threadIdx.x;
    if (i >= total) return;
    float4 v = *(const float4*)(g_xl1 + (size_t)i * 4);
    __half2 h0 = __float22half2_rn(make_float2(v.x, v.y));
    __half2 h1 = __float22half2_rn(make_float2(v.z, v.w));
    uint2 u;
    u.x = *reinterpret_cast<unsigned*>(&h0);
    u.y = *reinterpret_cast<unsigned*>(&h1);
    g_xl1h[i] = u;
}

__global__ void to_half2(int total)   // total = N*32 elements
{
    int i = blockIdx.x * blockDim.x + threadIdx.x;
    if (i >= total) return;
    g_xl2h[i] = __float2half(g_xl2[i]);
}

// ---------------- fused dense transform: out = X @ W^T (+bias), K=128 ----------------
__global__ void transform_kernel(
    const float* __restrict__ X, int n,
    const float* __restrict__ W0, const float* __restrict__ W1, const float* __restrict__ W2,
    int F0, int F1, int F2,
    const float* __restrict__ b0, const float* __restrict__ b1, const float* __restrict__ b2,
    float* __restrict__ o0, float* __restrict__ o1, float* __restrict__ o2,
    int ld0, int ld1, int ld2,
    const float* __restrict__ nscale,
    const float* __restrict__ nshift)
{
    __shared__ float Xs[64][68];
    __shared__ float Ws[64][68];
    const int rb = blockIdx.x * 64;
    const int fb = blockIdx.y * 64;
    const int tid = threadIdx.x;
    const int Ft = F0 + F1 + F2;

    const int tx = tid & 15, ty = tid >> 4;
    float acc[4][4];
    #pragma unroll
    for (int i = 0; i < 4; i++)
        #pragma unroll
        for (int j = 0; j < 4; j++) acc[i][j] = 0.f;

    for (int kk = 0; kk < 128; kk += 64) {
        #pragma unroll
        for (int it = 0; it < 4; it++) {
            int idx = it * 256 + tid;
            int r = idx >> 4;
            int kc = (idx & 15) << 2;
            float4 v = make_float4(0.f, 0.f, 0.f, 0.f);
            int row = rb + r;
            if (row < n) {
                int c = kk + kc;
                v = *(const float4*)(X + (size_t)row * 128 + c);
                if (nscale) {
                    float4 sc = *(const float4*)(nscale + c);
                    float4 sh = *(const float4*)(nshift + c);
                    float a0 = v.x * sc.x + sh.x;
                    float a1 = v.y * sc.y + sh.y;
                    float a2 = v.z * sc.z + sh.z;
                    float a3 = v.w * sc.w + sh.w;
                    v.x = a0 > 0.f ? a0 : expm1f(a0);
                    v.y = a1 > 0.f ? a1 : expm1f(a1);
                    v.z = a2 > 0.f ? a2 : expm1f(a2);
                    v.w = a3 > 0.f ? a3 : expm1f(a3);
                }
            }
            Xs[r][kc] = v.x; Xs[r][kc + 1] = v.y; Xs[r][kc + 2] = v.z; Xs[r][kc + 3] = v.w;
        }
        #pragma unroll
        for (int it = 0; it < 4; it++) {
            int idx = it * 256 + tid;
            int f = idx >> 4;
            int kc = (idx & 15) << 2;
            int gf = fb + f;
            float4 v = make_float4(0.f, 0.f, 0.f, 0.f);
            const float* Wp = nullptr;
            int lf = gf;
            if (gf < F0) { Wp = W0; }
            else if (gf < F0 + F1) { Wp = W1; lf = gf - F0; }
            else if (gf < Ft) { Wp = W2; lf = gf - F0 - F1; }
            if (Wp) v = *(const float4*)(Wp + (size_t)lf * 128 + kk + kc);
            Ws[f][kc] = v.x; Ws[f][kc + 1] = v.y; Ws[f][kc + 2] = v.z; Ws[f][kc + 3] = v.w;
        }
        __syncthreads();

        #pragma unroll 8
        for (int k = 0; k < 64; k++) {
            float a[4], b[4];
            #pragma unroll
            for (int i = 0; i < 4; i++) a[i] = Xs[ty * 4 + i][k];
            #pragma unroll
            for (int j = 0; j < 4; j++) b[j] = Ws[tx * 4 + j][k];
            #pragma unroll
            for (int i = 0; i < 4; i++)
                #pragma unroll
                for (int j = 0; j < 4; j++) acc[i][j] += a[i] * b[j];
        }
        __syncthreads();
    }

    #pragma unroll
    for (int i = 0; i < 4; i++) {
        int row = rb + ty * 4 + i;
        if (row >= n) break;
        #pragma unroll
        for (int j = 0; j < 4; j++) {
            int gf = fb + tx * 4 + j;
            if (gf < F0) {
                float bb = b0 ? b0[gf] : 0.f;
                o0[(size_t)row * ld0 + gf] = acc[i][j] + bb;
            } else if (gf < F0 + F1) {
                int lf = gf - F0;
                float bb = b1 ? b1[lf] : 0.f;
                o1[(size_t)row * ld1 + lf] = acc[i][j] + bb;
            } else if (gf < Ft) {
                int lf = gf - F0 - F1;
                float bb = b2 ? b2[lf] : 0.f;
                o2[(size_t)row * ld2 + lf] = acc[i][j] + bb;
            }
        }
    }
}

// ---------------- conv1 aggregation + fused BN1 stats ----------------
// warp per destination node; lane owns channels [4*lane, 4*lane+4); head = lane>>3.
// Gathers HALF xl copies; math in fp32. Output stored normalized (no bias).
__global__ void agg_conv1(int N, const float* __restrict__ att)
{
    int w = (blockIdx.x * blockDim.x + threadIdx.x) >> 5;
    int lane = threadIdx.x & 31;
    int wl = threadIdx.x >> 5;
    float4 nv = make_float4(0.f, 0.f, 0.f, 0.f);

    if (w < N) {
        int beg = g_off[w], end = g_off[w + 1];
        float4 xr = *(const float4*)(g_xr1 + (size_t)w * 128 + lane * 4);
        float4 at = *(const float4*)(att + lane * 4);
        float4 acc = make_float4(0.f, 0.f, 0.f, 0.f);
        float den = 0.f;

        for (int j = beg; j < end; j++) {
            int s = g_csr[j];
            uint2 u = g_xl1h[(size_t)s * 32 + lane];
            float2 f0 = __half22float2(*reinterpret_cast<__half2*>(&u.x));
            float2 f1 = __half22float2(*reinterpret_cast<__half2*>(&u.y));
            float m0 = f0.x + xr.x, m1 = f0.y + xr.y, m2 = f1.x + xr.z, m3 = f1.y + xr.w;
            float l = (m0 > 0.f ? m0 : 0.2f * m0) * at.x
                    + (m1 > 0.f ? m1 : 0.2f * m1) * at.y
                    + (m2 > 0.f ? m2 : 0.2f * m2) * at.z
                    + (m3 > 0.f ? m3 : 0.2f * m3) * at.w;
            l += __shfl_xor_sync(0xffffffffu, l, 1);
            l += __shfl_xor_sync(0xffffffffu, l, 2);
            l += __shfl_xor_sync(0xffffffffu, l, 4);
            float a = expf(l);
            acc.x += a * f0.x; acc.y += a * f0.y; acc.z += a * f1.x; acc.w += a * f1.y;
            den += a;
        }
        float inv = __fdividef(1.f, den + 1e-16f);
        nv.x = acc.x * inv; nv.y = acc.y * inv; nv.z = acc.z * inv; nv.w = acc.w * inv;
        *(float4*)(g_agg1 + (size_t)w * 128 + lane * 4) = nv;
    }

    // fused BN stats: block-reduce over the 8 warps, then f64 reductions
    __shared__ float rs[8][32][4];
    __shared__ float rq[8][32][4];
    rs[wl][lane][0] = nv.x; rs[wl][lane][1] = nv.y; rs[wl][lane][2] = nv.z; rs[wl][lane][3] = nv.w;
    rq[wl][lane][0] = nv.x * nv.x; rq[wl][lane][1] = nv.y * nv.y;
    rq[wl][lane][2] = nv.z * nv.z; rq[wl][lane][3] = nv.w * nv.w;
    __syncthreads();
    if (threadIdx.x < 128) {
        int l = threadIdx.x >> 2, k = threadIdx.x & 3;
        float s = 0.f, q = 0.f;
        #pragma unroll
        for (int ww = 0; ww < 8; ww++) { s += rs[ww][l][k]; q += rq[ww][l][k]; }
        atomicAdd(&g_sum1[l * 4 + k], (double)s);
        atomicAdd(&g_sq1[l * 4 + k], (double)q);
    }
}

// ---------------- conv2 aggregation + fused BN2 stats ----------------
__global__ void agg_conv2(int N, const float* __restrict__ att)
{
    int w = (blockIdx.x * blockDim.x + threadIdx.x) >> 5;
    int lane = threadIdx.x & 31;
    int wl = threadIdx.x >> 5;
    float nv = 0.f;

    if (w < N) {
        int beg = g_off[w], end = g_off[w + 1];
        float xr = g_xr2[(size_t)w * 32 + lane];
        float attc = att[lane];
        float acc = 0.f, den = 0.f;

        for (int j = beg; j < end; j++) {
            int s = g_csr[j];
            float xl = __half2float(g_xl2h[(size_t)s * 32 + lane]);
            float m = xl + xr;
            float l = (m > 0.f ? m : 0.2f * m) * attc;
            #pragma unroll
            for (int o = 16; o > 0; o >>= 1) l += __shfl_xor_sync(0xffffffffu, l, o);
            float a = expf(l);
            acc += a * xl;
            den += a;
        }
        nv = acc * __fdividef(1.f, den + 1e-16f);
        g_agg2[(size_t)w * 32 + lane] = nv;
    }

    __shared__ float rs[8][32];
    __shared__ float rq[8][32];
    rs[wl][lane] = nv;
    rq[wl][lane] = nv * nv;
    __syncthreads();
    if (threadIdx.x < 32) {
        float s = 0.f, q = 0.f;
        #pragma unroll
        for (int ww = 0; ww < 8; ww++) { s += rs[ww][threadIdx.x]; q += rq[ww][threadIdx.x]; }
        atomicAdd(&g_sum2[threadIdx.x], (double)s);
        atomicAdd(&g_sq2[threadIdx.x], (double)q);
    }
}

// ---------------- BN prep: stats over raw normalized agg (no bias) ----------------
// value fed downstream = agg*scale + shift, where
// scale = g*rsqrt(var+eps), shift = -mu*scale + b  (bias folds out exactly)
__global__ void bn_prep(const double* __restrict__ sum, const double* __restrict__ sq,
                        int n, int C,
                        const float* __restrict__ g, const float* __restrict__ b,
                        float* __restrict__ scale, float* __restrict__ shift)
{
    int c = threadIdx.x;
    if (c >= C) return;
    double mu = sum[c] / n;
    double var = sq[c] / n - mu * mu;
    float istd = rsqrtf((float)var + 1e-5f);
    float sc = istd * g[c];
    scale[c] = sc;
    shift[c] = -(float)mu * sc + b[c];
}

// ---------------- final: BN2 + residual + ELU + [N,32]@[32,2] head ----------------
__global__ void finalize_kernel(const float* __restrict__ linW, const float* __restrict__ linb,
                                float* __restrict__ out, int n)
{
    int gw = (blockIdx.x * blockDim.x + threadIdx.x) >> 5;
    int lane = threadIdx.x & 31;
    if (gw >= n) return;
    float v = g_agg2[(size_t)gw * 32 + lane] * g_scale2[lane] + g_shift2[lane]
            + g_res[(size_t)gw * 32 + lane];
    v = v > 0.f ? v : expm1f(v);
    float o0 = v * linW[lane];
    float o1 = v * linW[32 + lane];
    #pragma unroll
    for (int o = 16; o > 0; o >>= 1) {
        o0 += __shfl_xor_sync(0xffffffffu, o0, o);
        o1 += __shfl_xor_sync(0xffffffffu, o1, o);
    }
    if (lane == 0) {
        out[(size_t)gw * 2] = o0 + linb[0];
        out[(size_t)gw * 2 + 1] = o1 + linb[1];
    }
}

// ---------------- host launcher ----------------
extern "C" void kernel_launch(void* const* d_in, const int* in_sizes, int n_in,
                              void* d_out, int out_size)
{
    const float* x      = (const float*)d_in[0];
    const int*   ei     = (const int*)d_in[1];
    const float* Wl1    = (const float*)d_in[2];
    const float* bl1    = (const float*)d_in[3];
    const float* Wr1    = (const float*)d_in[4];
    const float* br1    = (const float*)d_in[5];
    const float* att1   = (const float*)d_in[6];
    const float* bias1  = (const float*)d_in[7];
    const float* Wl2    = (const float*)d_in[8];
    const float* bl2    = (const float*)d_in[9];
    const float* Wr2    = (const float*)d_in[10];
    const float* br2    = (const float*)d_in[11];
    const float* att2   = (const float*)d_in[12];
    const float* bias2  = (const float*)d_in[13];
    const float* bn1_g  = (const float*)d_in[14];
    const float* bn1_b  = (const float*)d_in[15];
    const float* bn2_g  = (const float*)d_in[16];
    const float* bn2_b  = (const float*)d_in[17];
    const float* skipW  = (const float*)d_in[18];
    const float* linW   = (const float*)d_in[19];
    const float* linb   = (const float*)d_in[20];
    float* out = (float*)d_out;
    (void)bias1; (void)bias2;   // folded into BN algebra (mean shift cancels)

    const int N = in_sizes[0] / 128;
    const int E = in_sizes[1] / 2;
    const int EP = E + N;

    void* p;
    cudaGetSymbolAddress(&p, g_sum1); cudaMemsetAsync(p, 0, 128 * sizeof(double));
    cudaGetSymbolAddress(&p, g_sq1);  cudaMemsetAsync(p, 0, 128 * sizeof(double));
    cudaGetSymbolAddress(&p, g_sum2); cudaMemsetAsync(p, 0, 32 * sizeof(double));
    cudaGetSymbolAddress(&p, g_sq2);  cudaMemsetAsync(p, 0, 32 * sizeof(double));

    float *d_xl1, *d_xr1, *d_res, *d_xl2, *d_xr2, *d_agg1;
    float *d_scale1, *d_shift1, *d_scale2, *d_shift2;
    double *d_sum1, *d_sq1, *d_sum2, *d_sq2;
    cudaGetSymbolAddress((void**)&d_xl1, g_xl1);
    cudaGetSymbolAddress((void**)&d_xr1, g_xr1);
    cudaGetSymbolAddress((void**)&d_res, g_res);
    cudaGetSymbolAddress((void**)&d_xl2, g_xl2);
    cudaGetSymbolAddress((void**)&d_xr2, g_xr2);
    cudaGetSymbolAddress((void**)&d_agg1, g_agg1);
    cudaGetSymbolAddress((void**)&d_scale1, g_scale1);
    cudaGetSymbolAddress((void**)&d_shift1, g_shift1);
    cudaGetSymbolAddress((void**)&d_scale2, g_scale2);
    cudaGetSymbolAddress((void**)&d_shift2, g_shift2);
    cudaGetSymbolAddress((void**)&d_sum1, g_sum1);
    cudaGetSymbolAddress((void**)&d_sq1, g_sq1);
    cudaGetSymbolAddress((void**)&d_sum2, g_sum2);
    cudaGetSymbolAddress((void**)&d_sq2, g_sq2);

    const int rowBlocks = (N + 63) / 64;
    const int nodeWarpBlocks = (N * 32 + 255) / 256;
    const int nbScan = (N + 511) / 512;

    // ---- CSR build (depends only on ei) ----
    csr_init<<<(N + 255) / 256, 256>>>(N);
    csr_hist<<<(E + 255) / 256, 256>>>(ei, E);
    csr_scan1<<<nbScan, 512>>>(N);
    csr_scan2<<<1, 128>>>(nbScan);
    csr_scan3<<<(N + 255) / 256, 256>>>(N, EP);
    csr_scatter<<<(EP + 255) / 256, 256>>>(ei, E, N);

    // conv1 transforms + residual: 288 features = Wl1(128) | Wr1(128) | skip(32)
    transform_kernel<<<dim3(rowBlocks, 5), 256>>>(
        x, N, Wl1, Wr1, skipW, 128, 128, 32,
        bl1, br1, nullptr,
        d_xl1, d_xr1, d_res, 128, 128, 32,
        nullptr, nullptr);

    to_half1<<<(N * 32 + 255) / 256, 256>>>(N * 32);
    agg_conv1<<<nodeWarpBlocks, 256>>>(N, att1);

    bn_prep<<<1, 128>>>(d_sum1, d_sq1, N, 128, bn1_g, bn1_b, d_scale1, d_shift1);

    // conv2 transforms reading agg1 with on-the-fly BN + ELU
    transform_kernel<<<dim3(rowBlocks, 1), 256>>>(
        d_agg1, N, Wl2, Wr2, nullptr, 32, 32, 0,
        bl2, br2, nullptr,
        d_xl2, d_xr2, nullptr, 32, 32, 0,
        d_scale1, d_shift1);

    to_half2<<<(N * 32 + 255) / 256, 256>>>(N * 32);
    agg_conv2<<<nodeWarpBlocks, 256>>>(N, att2);

    bn_prep<<<1, 32>>>(d_sum2, d_sq2, N, 32, bn2_g, bn2_b, d_scale2, d_shift2);

    finalize_kernel<<<nodeWarpBlocks, 256>>>(linW, linb, out, N);
}

// round 8
// speedup vs baseline: 1.0808x; 1.0808x over previous
#include <cuda_runtime.h>
#include <cuda_fp16.h>
#include <math.h>

#define MAXN 50000
#define MAXE 800000

// ---------------- scratch (device globals; no allocation allowed) ----------------
__device__ float g_xl1[MAXN * 128];
__device__ float g_xr1[MAXN * 128];
__device__ uint2 g_xl1h[MAXN * 32];    // half2 x2 per uint2: 128 ch = 32 uint2/row
__device__ float g_res[MAXN * 32];
__device__ float g_agg1[MAXN * 128];   // normalized conv1 output (pre-bias)
__device__ float g_xl2[MAXN * 32];
__device__ __half g_xl2h[MAXN * 32];
__device__ float g_xr2[MAXN * 32];
__device__ float g_agg2[MAXN * 32];    // normalized conv2 output (pre-bias)
__device__ double g_sum1[128], g_sq1[128];
__device__ double g_sum2[32], g_sq2[32];
__device__ float g_scale1[128], g_shift1[128];
__device__ float g_scale2[32], g_shift2[32];
// CSR-by-destination (real edges only; self-loops handled inline)
__device__ int g_count[MAXN];
__device__ int g_off[MAXN + 1];
__device__ int g_cursor[MAXN];
__device__ int g_bsum[128];
__device__ int g_csr[MAXE];

// ---------------- CSR build ----------------
__global__ void csr_hist(const int* __restrict__ ei, int E) {
    int e = blockIdx.x * blockDim.x + threadIdx.x;
    if (e < E) atomicAdd(&g_count[ei[E + e]], 1);
}

__global__ void csr_scan1(int N) {
    __shared__ int sh[512];
    int tid = threadIdx.x;
    int i = blockIdx.x * 512 + tid;
    int v = (i < N) ? g_count[i] : 0;
    sh[tid] = v;
    __syncthreads();
    for (int ofs = 1; ofs < 512; ofs <<= 1) {
        int t = (tid >= ofs) ? sh[tid - ofs] : 0;
        __syncthreads();
        sh[tid] += t;
        __syncthreads();
    }
    if (i < N) g_off[i] = sh[tid] - v;
    if (tid == 511) g_bsum[blockIdx.x] = sh[511];
}

__global__ void csr_scan2(int nb) {
    __shared__ int sh[128];
    int tid = threadIdx.x;
    int v = (tid < nb) ? g_bsum[tid] : 0;
    sh[tid] = v;
    __syncthreads();
    for (int ofs = 1; ofs < 128; ofs <<= 1) {
        int t = (tid >= ofs) ? sh[tid - ofs] : 0;
        __syncthreads();
        sh[tid] += t;
        __syncthreads();
    }
    if (tid < nb) g_bsum[tid] = sh[tid] - v;
}

__global__ void csr_scan3(int N, int E) {
    int i = blockIdx.x * blockDim.x + threadIdx.x;
    if (i < N) {
        int o = g_off[i] + g_bsum[i >> 9];
        g_off[i] = o;
        g_cursor[i] = o;
    }
    if (i == 0) g_off[N] = E;
}

__global__ void csr_scatter(const int* __restrict__ ei, int E) {
    int e = blockIdx.x * blockDim.x + threadIdx.x;
    if (e >= E) return;
    int s = ei[e], d = ei[E + e];
    int pos = atomicAdd(&g_cursor[d], 1);
    g_csr[pos] = s;
}

// ---------------- half conversions ----------------
__global__ void to_half1(int total)   // total = N*32 uint2 slots
{
    int i = blockIdx.x * blockDim.x + threadIdx.x;
    if (i >= total) return;
    float4 v = *(const float4*)(g_xl1 + (size_t)i * 4);
    __half2 h0 = __float22half2_rn(make_float2(v.x, v.y));
    __half2 h1 = __float22half2_rn(make_float2(v.z, v.w));
    uint2 u;
    u.x = *reinterpret_cast<unsigned*>(&h0);
    u.y = *reinterpret_cast<unsigned*>(&h1);
    g_xl1h[i] = u;
}

__global__ void to_half2(int total)   // total = N*32 elements
{
    int i = blockIdx.x * blockDim.x + threadIdx.x;
    if (i >= total) return;
    g_xl2h[i] = __float2half(g_xl2[i]);
}

// ---------------- fused dense transform: out = X @ W^T (+bias), K=128 ----------------
__global__ void transform_kernel(
    const float* __restrict__ X, int n,
    const float* __restrict__ W0, const float* __restrict__ W1, const float* __restrict__ W2,
    int F0, int F1, int F2,
    const float* __restrict__ b0, const float* __restrict__ b1, const float* __restrict__ b2,
    float* __restrict__ o0, float* __restrict__ o1, float* __restrict__ o2,
    int ld0, int ld1, int ld2,
    const float* __restrict__ nscale,
    const float* __restrict__ nshift)
{
    __shared__ float Xs[64][68];
    __shared__ float Ws[64][68];
    const int rb = blockIdx.x * 64;
    const int fb = blockIdx.y * 64;
    const int tid = threadIdx.x;
    const int Ft = F0 + F1 + F2;

    const int tx = tid & 15, ty = tid >> 4;
    float acc[4][4];
    #pragma unroll
    for (int i = 0; i < 4; i++)
        #pragma unroll
        for (int j = 0; j < 4; j++) acc[i][j] = 0.f;

    for (int kk = 0; kk < 128; kk += 64) {
        #pragma unroll
        for (int it = 0; it < 4; it++) {
            int idx = it * 256 + tid;
            int r = idx >> 4;
            int kc = (idx & 15) << 2;
            float4 v = make_float4(0.f, 0.f, 0.f, 0.f);
            int row = rb + r;
            if (row < n) {
                int c = kk + kc;
                v = *(const float4*)(X + (size_t)row * 128 + c);
                if (nscale) {
                    float4 sc = *(const float4*)(nscale + c);
                    float4 sh = *(const float4*)(nshift + c);
                    float a0 = v.x * sc.x + sh.x;
                    float a1 = v.y * sc.y + sh.y;
                    float a2 = v.z * sc.z + sh.z;
                    float a3 = v.w * sc.w + sh.w;
                    v.x = a0 > 0.f ? a0 : expm1f(a0);
                    v.y = a1 > 0.f ? a1 : expm1f(a1);
                    v.z = a2 > 0.f ? a2 : expm1f(a2);
                    v.w = a3 > 0.f ? a3 : expm1f(a3);
                }
            }
            Xs[r][kc] = v.x; Xs[r][kc + 1] = v.y; Xs[r][kc + 2] = v.z; Xs[r][kc + 3] = v.w;
        }
        #pragma unroll
        for (int it = 0; it < 4; it++) {
            int idx = it * 256 + tid;
            int f = idx >> 4;
            int kc = (idx & 15) << 2;
            int gf = fb + f;
            float4 v = make_float4(0.f, 0.f, 0.f, 0.f);
            const float* Wp = nullptr;
            int lf = gf;
            if (gf < F0) { Wp = W0; }
            else if (gf < F0 + F1) { Wp = W1; lf = gf - F0; }
            else if (gf < Ft) { Wp = W2; lf = gf - F0 - F1; }
            if (Wp) v = *(const float4*)(Wp + (size_t)lf * 128 + kk + kc);
            Ws[f][kc] = v.x; Ws[f][kc + 1] = v.y; Ws[f][kc + 2] = v.z; Ws[f][kc + 3] = v.w;
        }
        __syncthreads();

        #pragma unroll 8
        for (int k = 0; k < 64; k++) {
            float a[4], b[4];
            #pragma unroll
            for (int i = 0; i < 4; i++) a[i] = Xs[ty * 4 + i][k];
            #pragma unroll
            for (int j = 0; j < 4; j++) b[j] = Ws[tx * 4 + j][k];
            #pragma unroll
            for (int i = 0; i < 4; i++)
                #pragma unroll
                for (int j = 0; j < 4; j++) acc[i][j] += a[i] * b[j];
        }
        __syncthreads();
    }

    #pragma unroll
    for (int i = 0; i < 4; i++) {
        int row = rb + ty * 4 + i;
        if (row >= n) break;
        #pragma unroll
        for (int j = 0; j < 4; j++) {
            int gf = fb + tx * 4 + j;
            if (gf < F0) {
                float bb = b0 ? b0[gf] : 0.f;
                o0[(size_t)row * ld0 + gf] = acc[i][j] + bb;
            } else if (gf < F0 + F1) {
                int lf = gf - F0;
                float bb = b1 ? b1[lf] : 0.f;
                o1[(size_t)row * ld1 + lf] = acc[i][j] + bb;
            } else if (gf < Ft) {
                int lf = gf - F0 - F1;
                float bb = b2 ? b2[lf] : 0.f;
                o2[(size_t)row * ld2 + lf] = acc[i][j] + bb;
            }
        }
    }
}

// ---------------- conv1 edge term helper ----------------
__device__ __forceinline__ void edge_term1(
    int s, int lane, const float4& xr, const float4& at,
    float4& acc, float& den)
{
    uint2 u = g_xl1h[(size_t)s * 32 + lane];
    float2 f0 = __half22float2(*reinterpret_cast<__half2*>(&u.x));
    float2 f1 = __half22float2(*reinterpret_cast<__half2*>(&u.y));
    float m0 = f0.x + xr.x, m1 = f0.y + xr.y, m2 = f1.x + xr.z, m3 = f1.y + xr.w;
    float l = (m0 > 0.f ? m0 : 0.2f * m0) * at.x
            + (m1 > 0.f ? m1 : 0.2f * m1) * at.y
            + (m2 > 0.f ? m2 : 0.2f * m2) * at.z
            + (m3 > 0.f ? m3 : 0.2f * m3) * at.w;
    l += __shfl_xor_sync(0xffffffffu, l, 1);
    l += __shfl_xor_sync(0xffffffffu, l, 2);
    l += __shfl_xor_sync(0xffffffffu, l, 4);
    float a = expf(l);
    acc.x += a * f0.x; acc.y += a * f0.y; acc.z += a * f1.x; acc.w += a * f1.y;
    den += a;
}

// ---------------- conv1 aggregation: warp per destination node ----------------
__global__ void agg_conv1(int N, const float* __restrict__ att)
{
    int w = (blockIdx.x * blockDim.x + threadIdx.x) >> 5;
    int lane = threadIdx.x & 31;
    if (w >= N) return;
    int beg = g_off[w], end = g_off[w + 1];

    float4 xr = *(const float4*)(g_xr1 + (size_t)w * 128 + lane * 4);
    float4 at = *(const float4*)(att + lane * 4);
    float4 acc = make_float4(0.f, 0.f, 0.f, 0.f);
    float den = 0.f;

    edge_term1(w, lane, xr, at, acc, den);   // implicit self-loop
    for (int j = beg; j < end; j++)
        edge_term1(g_csr[j], lane, xr, at, acc, den);

    float inv = __fdividef(1.f, den + 1e-16f);
    acc.x *= inv; acc.y *= inv; acc.z *= inv; acc.w *= inv;
    *(float4*)(g_agg1 + (size_t)w * 128 + lane * 4) = acc;
}

// ---------------- conv2 edge term helper ----------------
__device__ __forceinline__ void edge_term2(
    int s, int lane, float xr, float attc, float& acc, float& den)
{
    float xl = __half2float(g_xl2h[(size_t)s * 32 + lane]);
    float m = xl + xr;
    float l = (m > 0.f ? m : 0.2f * m) * attc;
    #pragma unroll
    for (int o = 16; o > 0; o >>= 1) l += __shfl_xor_sync(0xffffffffu, l, o);
    float a = expf(l);
    acc += a * xl;
    den += a;
}

// ---------------- conv2 aggregation: warp per destination node, 1 ch/lane ----------------
__global__ void agg_conv2(int N, const float* __restrict__ att)
{
    int w = (blockIdx.x * blockDim.x + threadIdx.x) >> 5;
    int lane = threadIdx.x & 31;
    if (w >= N) return;
    int beg = g_off[w], end = g_off[w + 1];

    float xr = g_xr2[(size_t)w * 32 + lane];
    float attc = att[lane];
    float acc = 0.f, den = 0.f;

    edge_term2(w, lane, xr, attc, acc, den);   // implicit self-loop
    for (int j = beg; j < end; j++)
        edge_term2(g_csr[j], lane, xr, attc, acc, den);

    g_agg2[(size_t)w * 32 + lane] = acc * __fdividef(1.f, den + 1e-16f);
}

// ---------------- batch-norm statistics over raw normalized agg (no bias) ----------------
template <int C>
__global__ void bn_stats(const float* __restrict__ h, int n,
                         double* __restrict__ sum, double* __restrict__ sq)
{
    const int Q = C / 4;
    int tid = threadIdx.x;
    float s0 = 0.f, s1 = 0.f, s2v = 0.f, s3 = 0.f;
    float t0 = 0.f, t1 = 0.f, t2 = 0.f, t3 = 0.f;
    size_t total4 = (size_t)n * Q;
    const float4* h4 = (const float4*)h;
    for (size_t j = (size_t)blockIdx.x * blockDim.x + tid; j < total4;
         j += (size_t)gridDim.x * blockDim.x) {
        float4 v = h4[j];
        s0 += v.x; t0 += v.x * v.x;
        s1 += v.y; t1 += v.y * v.y;
        s2v += v.z; t2 += v.z * v.z;
        s3 += v.w; t3 += v.w * v.w;
    }
    __shared__ float red[8][256];
    red[0][tid] = s0; red[1][tid] = s1; red[2][tid] = s2v; red[3][tid] = s3;
    red[4][tid] = t0; red[5][tid] = t1; red[6][tid] = t2; red[7][tid] = t3;
    __syncthreads();
    int q = tid & (Q - 1);
    if (tid < Q) {
        const int G = 256 / Q;
        #pragma unroll
        for (int k = 0; k < 8; k++) {
            float acc = 0.f;
            for (int r = 0; r < G; r++) acc += red[k][q + r * Q];
            if (k < 4) atomicAdd(&sum[q * 4 + k], (double)acc);
            else       atomicAdd(&sq[q * 4 + (k - 4)], (double)acc);
        }
    }
}

// ---------------- BN prep ----------------
// downstream value = agg*scale + shift; scale = g*rsqrt(var+eps), shift = -mu*scale + b
__global__ void bn_prep(const double* __restrict__ sum, const double* __restrict__ sq,
                        int n, int C,
                        const float* __restrict__ g, const float* __restrict__ b,
                        float* __restrict__ scale, float* __restrict__ shift)
{
    int c = threadIdx.x;
    if (c >= C) return;
    double mu = sum[c] / n;
    double var = sq[c] / n - mu * mu;
    float istd = rsqrtf((float)var + 1e-5f);
    float sc = istd * g[c];
    scale[c] = sc;
    shift[c] = -(float)mu * sc + b[c];
}

// ---------------- final: BN2 + residual + ELU + [N,32]@[32,2] head ----------------
__global__ void finalize_kernel(const float* __restrict__ linW, const float* __restrict__ linb,
                                float* __restrict__ out, int n)
{
    int gw = (blockIdx.x * blockDim.x + threadIdx.x) >> 5;
    int lane = threadIdx.x & 31;
    if (gw >= n) return;
    float v = g_agg2[(size_t)gw * 32 + lane] * g_scale2[lane] + g_shift2[lane]
            + g_res[(size_t)gw * 32 + lane];
    v = v > 0.f ? v : expm1f(v);
    float o0 = v * linW[lane];
    float o1 = v * linW[32 + lane];
    #pragma unroll
    for (int o = 16; o > 0; o >>= 1) {
        o0 += __shfl_xor_sync(0xffffffffu, o0, o);
        o1 += __shfl_xor_sync(0xffffffffu, o1, o);
    }
    if (lane == 0) {
        out[(size_t)gw * 2] = o0 + linb[0];
        out[(size_t)gw * 2 + 1] = o1 + linb[1];
    }
}

// ---------------- host launcher ----------------
extern "C" void kernel_launch(void* const* d_in, const int* in_sizes, int n_in,
                              void* d_out, int out_size)
{
    const float* x      = (const float*)d_in[0];
    const int*   ei     = (const int*)d_in[1];
    const float* Wl1    = (const float*)d_in[2];
    const float* bl1    = (const float*)d_in[3];
    const float* Wr1    = (const float*)d_in[4];
    const float* br1    = (const float*)d_in[5];
    const float* att1   = (const float*)d_in[6];
    const float* bias1  = (const float*)d_in[7];
    const float* Wl2    = (const float*)d_in[8];
    const float* bl2    = (const float*)d_in[9];
    const float* Wr2    = (const float*)d_in[10];
    const float* br2    = (const float*)d_in[11];
    const float* att2   = (const float*)d_in[12];
    const float* bias2  = (const float*)d_in[13];
    const float* bn1_g  = (const float*)d_in[14];
    const float* bn1_b  = (const float*)d_in[15];
    const float* bn2_g  = (const float*)d_in[16];
    const float* bn2_b  = (const float*)d_in[17];
    const float* skipW  = (const float*)d_in[18];
    const float* linW   = (const float*)d_in[19];
    const float* linb   = (const float*)d_in[20];
    float* out = (float*)d_out;
    (void)bias1; (void)bias2;   // bias folds out of BN exactly (mean shift)

    const int N = in_sizes[0] / 128;
    const int E = in_sizes[1] / 2;

    void* p;
    cudaGetSymbolAddress(&p, g_count); cudaMemsetAsync(p, 0, (size_t)N * sizeof(int));
    cudaGetSymbolAddress(&p, g_sum1);  cudaMemsetAsync(p, 0, 128 * sizeof(double));
    cudaGetSymbolAddress(&p, g_sq1);   cudaMemsetAsync(p, 0, 128 * sizeof(double));
    cudaGetSymbolAddress(&p, g_sum2);  cudaMemsetAsync(p, 0, 32 * sizeof(double));
    cudaGetSymbolAddress(&p, g_sq2);   cudaMemsetAsync(p, 0, 32 * sizeof(double));

    float *d_xl1, *d_xr1, *d_res, *d_xl2, *d_xr2, *d_agg1, *d_agg2;
    float *d_scale1, *d_shift1, *d_scale2, *d_shift2;
    double *d_sum1, *d_sq1, *d_sum2, *d_sq2;
    cudaGetSymbolAddress((void**)&d_xl1, g_xl1);
    cudaGetSymbolAddress((void**)&d_xr1, g_xr1);
    cudaGetSymbolAddress((void**)&d_res, g_res);
    cudaGetSymbolAddress((void**)&d_xl2, g_xl2);
    cudaGetSymbolAddress((void**)&d_xr2, g_xr2);
    cudaGetSymbolAddress((void**)&d_agg1, g_agg1);
    cudaGetSymbolAddress((void**)&d_agg2, g_agg2);
    cudaGetSymbolAddress((void**)&d_scale1, g_scale1);
    cudaGetSymbolAddress((void**)&d_shift1, g_shift1);
    cudaGetSymbolAddress((void**)&d_scale2, g_scale2);
    cudaGetSymbolAddress((void**)&d_shift2, g_shift2);
    cudaGetSymbolAddress((void**)&d_sum1, g_sum1);
    cudaGetSymbolAddress((void**)&d_sq1, g_sq1);
    cudaGetSymbolAddress((void**)&d_sum2, g_sum2);
    cudaGetSymbolAddress((void**)&d_sq2, g_sq2);

    const int rowBlocks = (N + 63) / 64;
    const int nodeWarpBlocks = (N * 32 + 255) / 256;
    const int nbScan = (N + 511) / 512;

    // ---- CSR build (real edges only) ----
    csr_hist<<<(E + 255) / 256, 256>>>(ei, E);
    csr_scan1<<<nbScan, 512>>>(N);
    csr_scan2<<<1, 128>>>(nbScan);
    csr_scan3<<<(N + 255) / 256, 256>>>(N, E);
    csr_scatter<<<(E + 255) / 256, 256>>>(ei, E);

    // conv1 transforms + residual: 288 features = Wl1(128) | Wr1(128) | skip(32)
    transform_kernel<<<dim3(rowBlocks, 5), 256>>>(
        x, N, Wl1, Wr1, skipW, 128, 128, 32,
        bl1, br1, nullptr,
        d_xl1, d_xr1, d_res, 128, 128, 32,
        nullptr, nullptr);

    to_half1<<<(N * 32 + 255) / 256, 256>>>(N * 32);
    agg_conv1<<<nodeWarpBlocks, 256>>>(N, att1);

    bn_stats<128><<<256, 256>>>(d_agg1, N, d_sum1, d_sq1);
    bn_prep<<<1, 128>>>(d_sum1, d_sq1, N, 128, bn1_g, bn1_b, d_scale1, d_shift1);

    // conv2 transforms reading agg1 with on-the-fly BN + ELU
    transform_kernel<<<dim3(rowBlocks, 1), 256>>>(
        d_agg1, N, Wl2, Wr2, nullptr, 32, 32, 0,
        bl2, br2, nullptr,
        d_xl2, d_xr2, nullptr, 32, 32, 0,
        d_scale1, d_shift1);

    to_half2<<<(N * 32 + 255) / 256, 256>>>(N * 32);
    agg_conv2<<<nodeWarpBlocks, 256>>>(N, att2);

    bn_stats<32><<<256, 256>>>(d_agg2, N, d_sum2, d_sq2);
    bn_prep<<<1, 32>>>(d_sum2, d_sq2, N, 32, bn2_g, bn2_b, d_scale2, d_shift2);

    finalize_kernel<<<nodeWarpBlocks, 256>>>(linW, linb, out, N);
}

// round 10
// speedup vs baseline: 1.1767x; 1.0887x over previous
#include <cuda_runtime.h>
#include <cuda_fp16.h>
#include <math.h>

#define MAXN 50000
#define MAXE 800000

// ---------------- scratch (device globals; no allocation allowed) ----------------
__device__ __half g_xl1h[MAXN * 128];
__device__ float g_xr1[MAXN * 128];
__device__ float g_res[MAXN * 32];
__device__ float g_agg1[MAXN * 128];   // normalized conv1 output (pre-bias)
__device__ __half g_xl2h[MAXN * 32];
__device__ float g_xr2[MAXN * 32];
__device__ float g_agg2[MAXN * 32];    // normalized conv2 output (pre-bias)
__device__ double g_sum1[128], g_sq1[128];
__device__ double g_sum2[32], g_sq2[32];
__device__ float g_scale1[128], g_shift1[128];
__device__ float g_scale2[32], g_shift2[32];
// CSR-by-destination (real edges only; self-loops handled inline)
__device__ int g_count[MAXN];
__device__ int g_off[MAXN];
__device__ int g_cursor[MAXN];
__device__ int g_total;
__device__ int g_csr[MAXE];

// ---------------- CSR build ----------------
__global__ void csr_hist(const int* __restrict__ ei, int E) {
    int e = blockIdx.x * blockDim.x + threadIdx.x;
    if (e < E) atomicAdd(&g_count[ei[E + e]], 1);
}

// warp-aggregated offset allocation: contiguous slot range per node, order arbitrary
__global__ void csr_alloc(int N) {
    int i = blockIdx.x * blockDim.x + threadIdx.x;
    int lane = threadIdx.x & 31;
    int c = (i < N) ? g_count[i] : 0;
    int pre = c;
    #pragma unroll
    for (int o = 1; o < 32; o <<= 1) {
        int t = __shfl_up_sync(0xffffffffu, pre, o);
        if (lane >= o) pre += t;
    }
    int wsum = __shfl_sync(0xffffffffu, pre, 31);
    int base = 0;
    if (lane == 31) base = atomicAdd(&g_total, wsum);
    base = __shfl_sync(0xffffffffu, base, 31);
    if (i < N) {
        int off = base + pre - c;
        g_off[i] = off;
        g_cursor[i] = off;
    }
}

__global__ void csr_scatter(const int* __restrict__ ei, int E) {
    int e = blockIdx.x * blockDim.x + threadIdx.x;
    if (e >= E) return;
    int s = ei[e], d = ei[E + e];
    int pos = atomicAdd(&g_cursor[d], 1);
    g_csr[pos] = s;
}

// ---------------- fused dense transform: out = X @ W^T (+bias), K=128 ----------------
// o0 is written as HALF (o0h); o1/o2 as float. Optional input transform
// (nscale/nshift): v -> elu(v*scale + shift), used for conv2 reading agg1.
__global__ void transform_kernel(
    const float* __restrict__ X, int n,
    const float* __restrict__ W0, const float* __restrict__ W1, const float* __restrict__ W2,
    int F0, int F1, int F2,
    const float* __restrict__ b0, const float* __restrict__ b1, const float* __restrict__ b2,
    __half* __restrict__ o0h, float* __restrict__ o1, float* __restrict__ o2,
    int ld0, int ld1, int ld2,
    const float* __restrict__ nscale,
    const float* __restrict__ nshift)
{
    __shared__ float Xs[64][68];
    __shared__ float Ws[64][68];
    const int rb = blockIdx.x * 64;
    const int fb = blockIdx.y * 64;
    const int tid = threadIdx.x;
    const int Ft = F0 + F1 + F2;

    const int tx = tid & 15, ty = tid >> 4;
    float acc[4][4];
    #pragma unroll
    for (int i = 0; i < 4; i++)
        #pragma unroll
        for (int j = 0; j < 4; j++) acc[i][j] = 0.f;

    for (int kk = 0; kk < 128; kk += 64) {
        #pragma unroll
        for (int it = 0; it < 4; it++) {
            int idx = it * 256 + tid;
            int r = idx >> 4;
            int kc = (idx & 15) << 2;
            float4 v = make_float4(0.f, 0.f, 0.f, 0.f);
            int row = rb + r;
            if (row < n) {
                int c = kk + kc;
                v = *(const float4*)(X + (size_t)row * 128 + c);
                if (nscale) {
                    float4 sc = *(const float4*)(nscale + c);
                    float4 sh = *(const float4*)(nshift + c);
                    float a0 = v.x * sc.x + sh.x;
                    float a1 = v.y * sc.y + sh.y;
                    float a2 = v.z * sc.z + sh.z;
                    float a3 = v.w * sc.w + sh.w;
                    v.x = a0 > 0.f ? a0 : expm1f(a0);
                    v.y = a1 > 0.f ? a1 : expm1f(a1);
                    v.z = a2 > 0.f ? a2 : expm1f(a2);
                    v.w = a3 > 0.f ? a3 : expm1f(a3);
                }
            }
            Xs[r][kc] = v.x; Xs[r][kc + 1] = v.y; Xs[r][kc + 2] = v.z; Xs[r][kc + 3] = v.w;
        }
        #pragma unroll
        for (int it = 0; it < 4; it++) {
            int idx = it * 256 + tid;
            int f = idx >> 4;
            int kc = (idx & 15) << 2;
            int gf = fb + f;
            float4 v = make_float4(0.f, 0.f, 0.f, 0.f);
            const float* Wp = nullptr;
            int lf = gf;
            if (gf < F0) { Wp = W0; }
            else if (gf < F0 + F1) { Wp = W1; lf = gf - F0; }
            else if (gf < Ft) { Wp = W2; lf = gf - F0 - F1; }
            if (Wp) v = *(const float4*)(Wp + (size_t)lf * 128 + kk + kc);
            Ws[f][kc] = v.x; Ws[f][kc + 1] = v.y; Ws[f][kc + 2] = v.z; Ws[f][kc + 3] = v.w;
        }
        __syncthreads();

        #pragma unroll 8
        for (int k = 0; k < 64; k++) {
            float a[4], b[4];
            #pragma unroll
            for (int i = 0; i < 4; i++) a[i] = Xs[ty * 4 + i][k];
            #pragma unroll
            for (int j = 0; j < 4; j++) b[j] = Ws[tx * 4 + j][k];
            #pragma unroll
            for (int i = 0; i < 4; i++)
                #pragma unroll
                for (int j = 0; j < 4; j++) acc[i][j] += a[i] * b[j];
        }
        __syncthreads();
    }

    const int gfb = fb + tx * 4;   // 4 consecutive features; Ft multiple of 4 => no straddle
    if (gfb < Ft) {
        #pragma unroll
        for (int i = 0; i < 4; i++) {
            int row = rb + ty * 4 + i;
            if (row >= n) break;
            if (gfb < F0) {
                float a0 = acc[i][0] + (b0 ? b0[gfb + 0] : 0.f);
                float a1 = acc[i][1] + (b0 ? b0[gfb + 1] : 0.f);
                float a2 = acc[i][2] + (b0 ? b0[gfb + 2] : 0.f);
                float a3 = acc[i][3] + (b0 ? b0[gfb + 3] : 0.f);
                __half2 p0 = __floats2half2_rn(a0, a1);
                __half2 p1 = __floats2half2_rn(a2, a3);
                uint2 u;
                u.x = *reinterpret_cast<unsigned*>(&p0);
                u.y = *reinterpret_cast<unsigned*>(&p1);
                *(uint2*)(o0h + (size_t)row * ld0 + gfb) = u;
            } else if (gfb < F0 + F1) {
                int lf = gfb - F0;
                #pragma unroll
                for (int j = 0; j < 4; j++)
                    o1[(size_t)row * ld1 + lf + j] = acc[i][j] + (b1 ? b1[lf + j] : 0.f);
            } else {
                int lf = gfb - F0 - F1;
                #pragma unroll
                for (int j = 0; j < 4; j++)
                    o2[(size_t)row * ld2 + lf + j] = acc[i][j] + (b2 ? b2[lf + j] : 0.f);
            }
        }
    }
}

// ---------------- conv1 edge term ----------------
__device__ __forceinline__ void term1(
    uint2 u, const float4& xr, const float4& at, float4& acc, float& den)
{
    float2 f0 = __half22float2(*reinterpret_cast<__half2*>(&u.x));
    float2 f1 = __half22float2(*reinterpret_cast<__half2*>(&u.y));
    float m0 = f0.x + xr.x, m1 = f0.y + xr.y, m2 = f1.x + xr.z, m3 = f1.y + xr.w;
    float l = (m0 > 0.f ? m0 : 0.2f * m0) * at.x
            + (m1 > 0.f ? m1 : 0.2f * m1) * at.y
            + (m2 > 0.f ? m2 : 0.2f * m2) * at.z
            + (m3 > 0.f ? m3 : 0.2f * m3) * at.w;
    l += __shfl_xor_sync(0xffffffffu, l, 1);
    l += __shfl_xor_sync(0xffffffffu, l, 2);
    l += __shfl_xor_sync(0xffffffffu, l, 4);
    float a = __expf(l);
    acc.x += a * f0.x; acc.y += a * f0.y; acc.z += a * f1.x; acc.w += a * f1.y;
    den += a;
}

// ---------------- conv1 aggregation: warp per node, 1-deep software pipeline ----------------
__global__ void agg_conv1(int N, const float* __restrict__ att)
{
    int w = (blockIdx.x * blockDim.x + threadIdx.x) >> 5;
    int lane = threadIdx.x & 31;
    if (w >= N) return;
    int beg = g_off[w], end = beg + g_count[w];

    float4 xr = *(const float4*)(g_xr1 + (size_t)w * 128 + lane * 4);
    float4 at = *(const float4*)(att + lane * 4);
    float4 acc = make_float4(0.f, 0.f, 0.f, 0.f);
    float den = 0.f;

    uint2 u_next = make_uint2(0u, 0u);
    if (beg < end) {
        int s0 = g_csr[beg];
        u_next = *(const uint2*)(g_xl1h + (size_t)s0 * 128 + lane * 4);
    }
    {
        uint2 u = *(const uint2*)(g_xl1h + (size_t)w * 128 + lane * 4);
        term1(u, xr, at, acc, den);   // implicit self-loop
    }
    for (int j = beg; j < end; j++) {
        uint2 u = u_next;
        if (j + 1 < end) {
            int sn = g_csr[j + 1];
            u_next = *(const uint2*)(g_xl1h + (size_t)sn * 128 + lane * 4);
        }
        term1(u, xr, at, acc, den);
    }
    float inv = __fdividef(1.f, den + 1e-16f);
    acc.x *= inv; acc.y *= inv; acc.z *= inv; acc.w *= inv;
    *(float4*)(g_agg1 + (size_t)w * 128 + lane * 4) = acc;
}

// ---------------- conv2 aggregation: warp per node, 4 edges per iteration ----------------
// 8-lane group per edge; sub-lane owns 4 channels (uint2 half load).
__global__ void agg_conv2(int N, const float* __restrict__ att)
{
    int w = (blockIdx.x * blockDim.x + threadIdx.x) >> 5;
    int lane = threadIdx.x & 31;
    if (w >= N) return;
    int beg = g_off[w];
    int T = g_count[w] + 1;
    int grp = lane >> 3, sl = lane & 7;

    float4 xr = *(const float4*)(g_xr2 + (size_t)w * 32 + sl * 4);
    float4 at = *(const float4*)(att + sl * 4);
    float4 acc = make_float4(0.f, 0.f, 0.f, 0.f);
    float den = 0.f;

    for (int t0 = 0; t0 < T; t0 += 4) {
        int t = t0 + grp;
        bool valid = t < T;
        int s = w;
        if (valid && t > 0) s = g_csr[beg + t - 1];
        uint2 u = *(const uint2*)(g_xl2h + (size_t)s * 32 + sl * 4);
        float2 f0 = __half22float2(*reinterpret_cast<__half2*>(&u.x));
        float2 f1 = __half22float2(*reinterpret_cast<__half2*>(&u.y));
        float m0 = f0.x + xr.x, m1 = f0.y + xr.y, m2 = f1.x + xr.z, m3 = f1.y + xr.w;
        float l = (m0 > 0.f ? m0 : 0.2f * m0) * at.x
                + (m1 > 0.f ? m1 : 0.2f * m1) * at.y
                + (m2 > 0.f ? m2 : 0.2f * m2) * at.z
                + (m3 > 0.f ? m3 : 0.2f * m3) * at.w;
        l += __shfl_xor_sync(0xffffffffu, l, 1);
        l += __shfl_xor_sync(0xffffffffu, l, 2);
        l += __shfl_xor_sync(0xffffffffu, l, 4);
        float a = valid ? __expf(l) : 0.f;
        acc.x += a * f0.x; acc.y += a * f0.y; acc.z += a * f1.x; acc.w += a * f1.y;
        den += a;
    }
    #pragma unroll
    for (int o = 8; o <= 16; o <<= 1) {
        acc.x += __shfl_xor_sync(0xffffffffu, acc.x, o);
        acc.y += __shfl_xor_sync(0xffffffffu, acc.y, o);
        acc.z += __shfl_xor_sync(0xffffffffu, acc.z, o);
        acc.w += __shfl_xor_sync(0xffffffffu, acc.w, o);
        den   += __shfl_xor_sync(0xffffffffu, den, o);
    }
    if (lane < 8) {
        float inv = __fdividef(1.f, den + 1e-16f);
        acc.x *= inv; acc.y *= inv; acc.z *= inv; acc.w *= inv;
        *(float4*)(g_agg2 + (size_t)w * 32 + sl * 4) = acc;
    }
}

// ---------------- batch-norm statistics over raw normalized agg (no bias) ----------------
template <int C>
__global__ void bn_stats(const float* __restrict__ h, int n,
                         double* __restrict__ sum, double* __restrict__ sq)
{
    const int Q = C / 4;
    int tid = threadIdx.x;
    float s0 = 0.f, s1 = 0.f, s2v = 0.f, s3 = 0.f;
    float t0 = 0.f, t1 = 0.f, t2 = 0.f, t3 = 0.f;
    size_t total4 = (size_t)n * Q;
    const float4* h4 = (const float4*)h;
    for (size_t j = (size_t)blockIdx.x * blockDim.x + tid; j < total4;
         j += (size_t)gridDim.x * blockDim.x) {
        float4 v = h4[j];
        s0 += v.x; t0 += v.x * v.x;
        s1 += v.y; t1 += v.y * v.y;
        s2v += v.z; t2 += v.z * v.z;
        s3 += v.w; t3 += v.w * v.w;
    }
    __shared__ float red[8][256];
    red[0][tid] = s0; red[1][tid] = s1; red[2][tid] = s2v; red[3][tid] = s3;
    red[4][tid] = t0; red[5][tid] = t1; red[6][tid] = t2; red[7][tid] = t3;
    __syncthreads();
    int q = tid & (Q - 1);
    if (tid < Q) {
        const int G = 256 / Q;
        #pragma unroll
        for (int k = 0; k < 8; k++) {
            float acc = 0.f;
            for (int r = 0; r < G; r++) acc += red[k][q + r * Q];
            if (k < 4) atomicAdd(&sum[q * 4 + k], (double)acc);
            else       atomicAdd(&sq[q * 4 + (k - 4)], (double)acc);
        }
    }
}

// ---------------- BN prep ----------------
// downstream value = agg*scale + shift; scale = g*rsqrt(var+eps), shift = -mu*scale + b
__global__ void bn_prep(const double* __restrict__ sum, const double* __restrict__ sq,
                        int n, int C,
                        const float* __restrict__ g, const float* __restrict__ b,
                        float* __restrict__ scale, float* __restrict__ shift)
{
    int c = threadIdx.x;
    if (c >= C) return;
    double mu = sum[c] / n;
    double var = sq[c] / n - mu * mu;
    float istd = rsqrtf((float)var + 1e-5f);
    float sc = istd * g[c];
    scale[c] = sc;
    shift[c] = -(float)mu * sc + b[c];
}

// ---------------- final: BN2 + residual + ELU + [N,32]@[32,2] head ----------------
__global__ void finalize_kernel(const float* __restrict__ linW, const float* __restrict__ linb,
                                float* __restrict__ out, int n)
{
    int gw = (blockIdx.x * blockDim.x + threadIdx.x) >> 5;
    int lane = threadIdx.x & 31;
    if (gw >= n) return;
    float v = g_agg2[(size_t)gw * 32 + lane] * g_scale2[lane] + g_shift2[lane]
            + g_res[(size_t)gw * 32 + lane];
    v = v > 0.f ? v : expm1f(v);
    float o0 = v * linW[lane];
    float o1 = v * linW[32 + lane];
    #pragma unroll
    for (int o = 16; o > 0; o >>= 1) {
        o0 += __shfl_xor_sync(0xffffffffu, o0, o);
        o1 += __shfl_xor_sync(0xffffffffu, o1, o);
    }
    if (lane == 0) {
        out[(size_t)gw * 2] = o0 + linb[0];
        out[(size_t)gw * 2 + 1] = o1 + linb[1];
    }
}

// ---------------- host launcher ----------------
extern "C" void kernel_launch(void* const* d_in, const int* in_sizes, int n_in,
                              void* d_out, int out_size)
{
    const float* x      = (const float*)d_in[0];
    const int*   ei     = (const int*)d_in[1];
    const float* Wl1    = (const float*)d_in[2];
    const float* bl1    = (const float*)d_in[3];
    const float* Wr1    = (const float*)d_in[4];
    const float* br1    = (const float*)d_in[5];
    const float* att1   = (const float*)d_in[6];
    const float* Wl2    = (const float*)d_in[8];
    const float* bl2    = (const float*)d_in[9];
    const float* Wr2    = (const float*)d_in[10];
    const float* br2    = (const float*)d_in[11];
    const float* att2   = (const float*)d_in[12];
    const float* bn1_g  = (const float*)d_in[14];
    const float* bn1_b  = (const float*)d_in[15];
    const float* bn2_g  = (const float*)d_in[16];
    const float* bn2_b  = (const float*)d_in[17];
    const float* skipW  = (const float*)d_in[18];
    const float* linW   = (const float*)d_in[19];
    const float* linb   = (const float*)d_in[20];
    float* out = (float*)d_out;
    // bias1/bias2 (d_in[7], d_in[13]) fold out of BN exactly (mean shift)

    const int N = in_sizes[0] / 128;
    const int E = in_sizes[1] / 2;

    void* p;
    cudaGetSymbolAddress(&p, g_count); cudaMemsetAsync(p, 0, (size_t)N * sizeof(int));
    cudaGetSymbolAddress(&p, g_total); cudaMemsetAsync(p, 0, sizeof(int));
    cudaGetSymbolAddress(&p, g_sum1);  cudaMemsetAsync(p, 0, 128 * sizeof(double));
    cudaGetSymbolAddress(&p, g_sq1);   cudaMemsetAsync(p, 0, 128 * sizeof(double));
    cudaGetSymbolAddress(&p, g_sum2);  cudaMemsetAsync(p, 0, 32 * sizeof(double));
    cudaGetSymbolAddress(&p, g_sq2);   cudaMemsetAsync(p, 0, 32 * sizeof(double));

    __half *d_xl1h, *d_xl2h;
    float *d_xr1, *d_res, *d_xr2, *d_agg1, *d_agg2;
    float *d_scale1, *d_shift1, *d_scale2, *d_shift2;
    double *d_sum1, *d_sq1, *d_sum2, *d_sq2;
    cudaGetSymbolAddress((void**)&d_xl1h, g_xl1h);
    cudaGetSymbolAddress((void**)&d_xr1, g_xr1);
    cudaGetSymbolAddress((void**)&d_res, g_res);
    cudaGetSymbolAddress((void**)&d_xl2h, g_xl2h);
    cudaGetSymbolAddress((void**)&d_xr2, g_xr2);
    cudaGetSymbolAddress((void**)&d_agg1, g_agg1);
    cudaGetSymbolAddress((void**)&d_agg2, g_agg2);
    cudaGetSymbolAddress((void**)&d_scale1, g_scale1);
    cudaGetSymbolAddress((void**)&d_shift1, g_shift1);
    cudaGetSymbolAddress((void**)&d_scale2, g_scale2);
    cudaGetSymbolAddress((void**)&d_shift2, g_shift2);
    cudaGetSymbolAddress((void**)&d_sum1, g_sum1);
    cudaGetSymbolAddress((void**)&d_sq1, g_sq1);
    cudaGetSymbolAddress((void**)&d_sum2, g_sum2);
    cudaGetSymbolAddress((void**)&d_sq2, g_sq2);

    const int rowBlocks = (N + 63) / 64;
    const int nodeWarpBlocks = (N * 32 + 255) / 256;

    // ---- CSR build: 3 kernels ----
    csr_hist<<<(E + 255) / 256, 256>>>(ei, E);          // launch 0
    csr_alloc<<<(N + 255) / 256, 256>>>(N);             // launch 1
    csr_scatter<<<(E + 255) / 256, 256>>>(ei, E);       // launch 2

    // conv1 transforms + residual (launch 3 — profiled by ncu)
    transform_kernel<<<dim3(rowBlocks, 5), 256>>>(
        x, N, Wl1, Wr1, skipW, 128, 128, 32,
        bl1, br1, nullptr,
        d_xl1h, d_xr1, d_res, 128, 128, 32,
        nullptr, nullptr);

    agg_conv1<<<nodeWarpBlocks, 256>>>(N, att1);

    bn_stats<128><<<256, 256>>>(d_agg1, N, d_sum1, d_sq1);
    bn_prep<<<1, 128>>>(d_sum1, d_sq1, N, 128, bn1_g, bn1_b, d_scale1, d_shift1);

    // conv2 transforms reading agg1 with on-the-fly BN + ELU
    transform_kernel<<<dim3(rowBlocks, 1), 256>>>(
        d_agg1, N, Wl2, Wr2, nullptr, 32, 32, 0,
        bl2, br2, nullptr,
        d_xl2h, d_xr2, nullptr, 32, 32, 0,
        d_scale1, d_shift1);

    agg_conv2<<<nodeWarpBlocks, 256>>>(N, att2);

    bn_stats<32><<<256, 256>>>(d_agg2, N, d_sum2, d_sq2);
    bn_prep<<<1, 32>>>(d_sum2, d_sq2, N, 32, bn2_g, bn2_b, d_scale2, d_shift2);

    finalize_kernel<<<nodeWarpBlocks, 256>>>(linW, linb, out, N);
}

// round 11
// speedup vs baseline: 1.6353x; 1.3898x over previous
#include <cuda_runtime.h>
#include <cuda_fp16.h>
#include <math.h>

#define MAXN 50000
#define MAXE 800000

// ---------------- scratch (device globals; no allocation allowed) ----------------
__device__ __half g_xl1h[MAXN * 128];
__device__ float g_xr1[MAXN * 128];
__device__ float g_res[MAXN * 32];
__device__ float g_agg1[MAXN * 128];   // normalized conv1 output (pre-bias)
__device__ __half g_xl2h[MAXN * 32];
__device__ float g_xr2[MAXN * 32];
__device__ float g_agg2[MAXN * 32];    // normalized conv2 output (pre-bias)
__device__ double g_sum1[128], g_sq1[128];
__device__ double g_sum2[32], g_sq2[32];
__device__ float g_scale1[128], g_shift1[128];
__device__ float g_scale2[32], g_shift2[32];
// CSR-by-destination (real edges only; self-loops handled inline)
__device__ int g_count[MAXN];
__device__ int g_off[MAXN];
__device__ int g_cursor[MAXN];
__device__ int g_total;
__device__ int g_csr[MAXE];

// ---------------- CSR build ----------------
__global__ void csr_hist(const int* __restrict__ ei, int E) {
    int e = blockIdx.x * blockDim.x + threadIdx.x;
    if (e < E) atomicAdd(&g_count[ei[E + e]], 1);
}

// warp-aggregated offset allocation: contiguous slot range per node, order arbitrary
__global__ void csr_alloc(int N) {
    int i = blockIdx.x * blockDim.x + threadIdx.x;
    int lane = threadIdx.x & 31;
    int c = (i < N) ? g_count[i] : 0;
    int pre = c;
    #pragma unroll
    for (int o = 1; o < 32; o <<= 1) {
        int t = __shfl_up_sync(0xffffffffu, pre, o);
        if (lane >= o) pre += t;
    }
    int wsum = __shfl_sync(0xffffffffu, pre, 31);
    int base = 0;
    if (lane == 31) base = atomicAdd(&g_total, wsum);
    base = __shfl_sync(0xffffffffu, base, 31);
    if (i < N) {
        int off = base + pre - c;
        g_off[i] = off;
        g_cursor[i] = off;
    }
}

__global__ void csr_scatter(const int* __restrict__ ei, int E) {
    int e = blockIdx.x * blockDim.x + threadIdx.x;
    if (e >= E) return;
    int s = ei[e], d = ei[E + e];
    int pos = atomicAdd(&g_cursor[d], 1);
    g_csr[pos] = s;
}

// ---------------- fused dense transform: out = X @ W^T (+bias), K=128 ----------------
// Smem tiles stored K-MAJOR (XsT[k][row], WsT[k][feat]) for conflict-free
// float4 shared loads in the FMA loop. Row stride 68 keeps 16B alignment.
// o0 written as HALF (o0h); o1/o2 as float. Optional input transform
// (nscale/nshift): v -> elu(v*scale + shift), used for conv2 reading agg1.
__global__ void transform_kernel(
    const float* __restrict__ X, int n,
    const float* __restrict__ W0, const float* __restrict__ W1, const float* __restrict__ W2,
    int F0, int F1, int F2,
    const float* __restrict__ b0, const float* __restrict__ b1, const float* __restrict__ b2,
    __half* __restrict__ o0h, float* __restrict__ o1, float* __restrict__ o2,
    int ld0, int ld1, int ld2,
    const float* __restrict__ nscale,
    const float* __restrict__ nshift)
{
    __shared__ float XsT[64][68];   // [k][row]
    __shared__ float WsT[64][68];   // [k][feat]
    const int rb = blockIdx.x * 64;
    const int fb = blockIdx.y * 64;
    const int tid = threadIdx.x;
    const int Ft = F0 + F1 + F2;

    const int tx = tid & 15, ty = tid >> 4;
    float acc[4][4];
    #pragma unroll
    for (int i = 0; i < 4; i++)
        #pragma unroll
        for (int j = 0; j < 4; j++) acc[i][j] = 0.f;

    for (int kk = 0; kk < 128; kk += 64) {
        #pragma unroll
        for (int it = 0; it < 4; it++) {
            int idx = it * 256 + tid;
            int r = idx >> 4;            // 0..63
            int kc = (idx & 15) << 2;    // 0..60
            float4 v = make_float4(0.f, 0.f, 0.f, 0.f);
            int row = rb + r;
            if (row < n) {
                int c = kk + kc;
                v = *(const float4*)(X + (size_t)row * 128 + c);
                if (nscale) {
                    float4 sc = *(const float4*)(nscale + c);
                    float4 sh = *(const float4*)(nshift + c);
                    float a0 = v.x * sc.x + sh.x;
                    float a1 = v.y * sc.y + sh.y;
                    float a2 = v.z * sc.z + sh.z;
                    float a3 = v.w * sc.w + sh.w;
                    v.x = a0 > 0.f ? a0 : expm1f(a0);
                    v.y = a1 > 0.f ? a1 : expm1f(a1);
                    v.z = a2 > 0.f ? a2 : expm1f(a2);
                    v.w = a3 > 0.f ? a3 : expm1f(a3);
                }
            }
            XsT[kc + 0][r] = v.x;
            XsT[kc + 1][r] = v.y;
            XsT[kc + 2][r] = v.z;
            XsT[kc + 3][r] = v.w;
        }
        #pragma unroll
        for (int it = 0; it < 4; it++) {
            int idx = it * 256 + tid;
            int f = idx >> 4;
            int kc = (idx & 15) << 2;
            int gf = fb + f;
            float4 v = make_float4(0.f, 0.f, 0.f, 0.f);
            const float* Wp = nullptr;
            int lf = gf;
            if (gf < F0) { Wp = W0; }
            else if (gf < F0 + F1) { Wp = W1; lf = gf - F0; }
            else if (gf < Ft) { Wp = W2; lf = gf - F0 - F1; }
            if (Wp) v = *(const float4*)(Wp + (size_t)lf * 128 + kk + kc);
            WsT[kc + 0][f] = v.x;
            WsT[kc + 1][f] = v.y;
            WsT[kc + 2][f] = v.z;
            WsT[kc + 3][f] = v.w;
        }
        __syncthreads();

        #pragma unroll 8
        for (int k = 0; k < 64; k++) {
            float4 a4 = *(const float4*)&XsT[k][ty * 4];
            float4 b4 = *(const float4*)&WsT[k][tx * 4];
            float a[4] = {a4.x, a4.y, a4.z, a4.w};
            float b[4] = {b4.x, b4.y, b4.z, b4.w};
            #pragma unroll
            for (int i = 0; i < 4; i++)
                #pragma unroll
                for (int j = 0; j < 4; j++) acc[i][j] += a[i] * b[j];
        }
        __syncthreads();
    }

    const int gfb = fb + tx * 4;   // 4 consecutive features; Ft multiple of 4 => no straddle
    if (gfb < Ft) {
        #pragma unroll
        for (int i = 0; i < 4; i++) {
            int row = rb + ty * 4 + i;
            if (row >= n) break;
            if (gfb < F0) {
                float a0 = acc[i][0] + (b0 ? b0[gfb + 0] : 0.f);
                float a1 = acc[i][1] + (b0 ? b0[gfb + 1] : 0.f);
                float a2 = acc[i][2] + (b0 ? b0[gfb + 2] : 0.f);
                float a3 = acc[i][3] + (b0 ? b0[gfb + 3] : 0.f);
                __half2 p0 = __floats2half2_rn(a0, a1);
                __half2 p1 = __floats2half2_rn(a2, a3);
                uint2 u;
                u.x = *reinterpret_cast<unsigned*>(&p0);
                u.y = *reinterpret_cast<unsigned*>(&p1);
                *(uint2*)(o0h + (size_t)row * ld0 + gfb) = u;
            } else if (gfb < F0 + F1) {
                int lf = gfb - F0;
                #pragma unroll
                for (int j = 0; j < 4; j++)
                    o1[(size_t)row * ld1 + lf + j] = acc[i][j] + (b1 ? b1[lf + j] : 0.f);
            } else {
                int lf = gfb - F0 - F1;
                #pragma unroll
                for (int j = 0; j < 4; j++)
                    o2[(size_t)row * ld2 + lf + j] = acc[i][j] + (b2 ? b2[lf + j] : 0.f);
            }
        }
    }
}

// ---------------- conv1 edge term ----------------
__device__ __forceinline__ void term1(
    uint2 u, const float4& xr, const float4& at, float4& acc, float& den)
{
    float2 f0 = __half22float2(*reinterpret_cast<__half2*>(&u.x));
    float2 f1 = __half22float2(*reinterpret_cast<__half2*>(&u.y));
    float m0 = f0.x + xr.x, m1 = f0.y + xr.y, m2 = f1.x + xr.z, m3 = f1.y + xr.w;
    float l = (m0 > 0.f ? m0 : 0.2f * m0) * at.x
            + (m1 > 0.f ? m1 : 0.2f * m1) * at.y
            + (m2 > 0.f ? m2 : 0.2f * m2) * at.z
            + (m3 > 0.f ? m3 : 0.2f * m3) * at.w;
    l += __shfl_xor_sync(0xffffffffu, l, 1);
    l += __shfl_xor_sync(0xffffffffu, l, 2);
    l += __shfl_xor_sync(0xffffffffu, l, 4);
    float a = __expf(l);
    acc.x += a * f0.x; acc.y += a * f0.y; acc.z += a * f1.x; acc.w += a * f1.y;
    den += a;
}

// ---------------- conv1 aggregation: warp per node, 1-deep software pipeline ----------------
__global__ void agg_conv1(int N, const float* __restrict__ att)
{
    int w = (blockIdx.x * blockDim.x + threadIdx.x) >> 5;
    int lane = threadIdx.x & 31;
    if (w >= N) return;
    int beg = g_off[w], end = beg + g_count[w];

    float4 xr = *(const float4*)(g_xr1 + (size_t)w * 128 + lane * 4);
    float4 at = *(const float4*)(att + lane * 4);
    float4 acc = make_float4(0.f, 0.f, 0.f, 0.f);
    float den = 0.f;

    uint2 u_next = make_uint2(0u, 0u);
    if (beg < end) {
        int s0 = g_csr[beg];
        u_next = *(const uint2*)(g_xl1h + (size_t)s0 * 128 + lane * 4);
    }
    {
        uint2 u = *(const uint2*)(g_xl1h + (size_t)w * 128 + lane * 4);
        term1(u, xr, at, acc, den);   // implicit self-loop
    }
    for (int j = beg; j < end; j++) {
        uint2 u = u_next;
        if (j + 1 < end) {
            int sn = g_csr[j + 1];
            u_next = *(const uint2*)(g_xl1h + (size_t)sn * 128 + lane * 4);
        }
        term1(u, xr, at, acc, den);
    }
    float inv = __fdividef(1.f, den + 1e-16f);
    acc.x *= inv; acc.y *= inv; acc.z *= inv; acc.w *= inv;
    *(float4*)(g_agg1 + (size_t)w * 128 + lane * 4) = acc;
}

// ---------------- conv2 aggregation: warp per node, 4 edges per iteration ----------------
__global__ void agg_conv2(int N, const float* __restrict__ att)
{
    int w = (blockIdx.x * blockDim.x + threadIdx.x) >> 5;
    int lane = threadIdx.x & 31;
    if (w >= N) return;
    int beg = g_off[w];
    int T = g_count[w] + 1;
    int grp = lane >> 3, sl = lane & 7;

    float4 xr = *(const float4*)(g_xr2 + (size_t)w * 32 + sl * 4);
    float4 at = *(const float4*)(att + sl * 4);
    float4 acc = make_float4(0.f, 0.f, 0.f, 0.f);
    float den = 0.f;

    for (int t0 = 0; t0 < T; t0 += 4) {
        int t = t0 + grp;
        bool valid = t < T;
        int s = w;
        if (valid && t > 0) s = g_csr[beg + t - 1];
        uint2 u = *(const uint2*)(g_xl2h + (size_t)s * 32 + sl * 4);
        float2 f0 = __half22float2(*reinterpret_cast<__half2*>(&u.x));
        float2 f1 = __half22float2(*reinterpret_cast<__half2*>(&u.y));
        float m0 = f0.x + xr.x, m1 = f0.y + xr.y, m2 = f1.x + xr.z, m3 = f1.y + xr.w;
        float l = (m0 > 0.f ? m0 : 0.2f * m0) * at.x
                + (m1 > 0.f ? m1 : 0.2f * m1) * at.y
                + (m2 > 0.f ? m2 : 0.2f * m2) * at.z
                + (m3 > 0.f ? m3 : 0.2f * m3) * at.w;
        l += __shfl_xor_sync(0xffffffffu, l, 1);
        l += __shfl_xor_sync(0xffffffffu, l, 2);
        l += __shfl_xor_sync(0xffffffffu, l, 4);
        float a = valid ? __expf(l) : 0.f;
        acc.x += a * f0.x; acc.y += a * f0.y; acc.z += a * f1.x; acc.w += a * f1.y;
        den += a;
    }
    #pragma unroll
    for (int o = 8; o <= 16; o <<= 1) {
        acc.x += __shfl_xor_sync(0xffffffffu, acc.x, o);
        acc.y += __shfl_xor_sync(0xffffffffu, acc.y, o);
        acc.z += __shfl_xor_sync(0xffffffffu, acc.z, o);
        acc.w += __shfl_xor_sync(0xffffffffu, acc.w, o);
        den   += __shfl_xor_sync(0xffffffffu, den, o);
    }
    if (lane < 8) {
        float inv = __fdividef(1.f, den + 1e-16f);
        acc.x *= inv; acc.y *= inv; acc.z *= inv; acc.w *= inv;
        *(float4*)(g_agg2 + (size_t)w * 32 + sl * 4) = acc;
    }
}

// ---------------- batch-norm statistics over raw normalized agg (no bias) ----------------
template <int C>
__global__ void bn_stats(const float* __restrict__ h, int n,
                         double* __restrict__ sum, double* __restrict__ sq)
{
    const int Q = C / 4;
    int tid = threadIdx.x;
    float s0 = 0.f, s1 = 0.f, s2v = 0.f, s3 = 0.f;
    float t0 = 0.f, t1 = 0.f, t2 = 0.f, t3 = 0.f;
    size_t total4 = (size_t)n * Q;
    const float4* h4 = (const float4*)h;
    for (size_t j = (size_t)blockIdx.x * blockDim.x + tid; j < total4;
         j += (size_t)gridDim.x * blockDim.x) {
        float4 v = h4[j];
        s0 += v.x; t0 += v.x * v.x;
        s1 += v.y; t1 += v.y * v.y;
        s2v += v.z; t2 += v.z * v.z;
        s3 += v.w; t3 += v.w * v.w;
    }
    __shared__ float red[8][256];
    red[0][tid] = s0; red[1][tid] = s1; red[2][tid] = s2v; red[3][tid] = s3;
    red[4][tid] = t0; red[5][tid] = t1; red[6][tid] = t2; red[7][tid] = t3;
    __syncthreads();
    int q = tid & (Q - 1);
    if (tid < Q) {
        const int G = 256 / Q;
        #pragma unroll
        for (int k = 0; k < 8; k++) {
            float acc = 0.f;
            for (int r = 0; r < G; r++) acc += red[k][q + r * Q];
            if (k < 4) atomicAdd(&sum[q * 4 + k], (double)acc);
            else       atomicAdd(&sq[q * 4 + (k - 4)], (double)acc);
        }
    }
}

// ---------------- BN prep ----------------
// downstream value = agg*scale + shift; scale = g*rsqrt(var+eps), shift = -mu*scale + b
__global__ void bn_prep(const double* __restrict__ sum, const double* __restrict__ sq,
                        int n, int C,
                        const float* __restrict__ g, const float* __restrict__ b,
                        float* __restrict__ scale, float* __restrict__ shift)
{
    int c = threadIdx.x;
    if (c >= C) return;
    double mu = sum[c] / n;
    double var = sq[c] / n - mu * mu;
    float istd = rsqrtf((float)var + 1e-5f);
    float sc = istd * g[c];
    scale[c] = sc;
    shift[c] = -(float)mu * sc + b[c];
}

// ---------------- final: BN2 + residual + ELU + [N,32]@[32,2] head ----------------
__global__ void finalize_kernel(const float* __restrict__ linW, const float* __restrict__ linb,
                                float* __restrict__ out, int n)
{
    int gw = (blockIdx.x * blockDim.x + threadIdx.x) >> 5;
    int lane = threadIdx.x & 31;
    if (gw >= n) return;
    float v = g_agg2[(size_t)gw * 32 + lane] * g_scale2[lane] + g_shift2[lane]
            + g_res[(size_t)gw * 32 + lane];
    v = v > 0.f ? v : expm1f(v);
    float o0 = v * linW[lane];
    float o1 = v * linW[32 + lane];
    #pragma unroll
    for (int o = 16; o > 0; o >>= 1) {
        o0 += __shfl_xor_sync(0xffffffffu, o0, o);
        o1 += __shfl_xor_sync(0xffffffffu, o1, o);
    }
    if (lane == 0) {
        out[(size_t)gw * 2] = o0 + linb[0];
        out[(size_t)gw * 2 + 1] = o1 + linb[1];
    }
}

// ---------------- host launcher ----------------
extern "C" void kernel_launch(void* const* d_in, const int* in_sizes, int n_in,
                              void* d_out, int out_size)
{
    const float* x      = (const float*)d_in[0];
    const int*   ei     = (const int*)d_in[1];
    const float* Wl1    = (const float*)d_in[2];
    const float* bl1    = (const float*)d_in[3];
    const float* Wr1    = (const float*)d_in[4];
    const float* br1    = (const float*)d_in[5];
    const float* att1   = (const float*)d_in[6];
    const float* Wl2    = (const float*)d_in[8];
    const float* bl2    = (const float*)d_in[9];
    const float* Wr2    = (const float*)d_in[10];
    const float* br2    = (const float*)d_in[11];
    const float* att2   = (const float*)d_in[12];
    const float* bn1_g  = (const float*)d_in[14];
    const float* bn1_b  = (const float*)d_in[15];
    const float* bn2_g  = (const float*)d_in[16];
    const float* bn2_b  = (const float*)d_in[17];
    const float* skipW  = (const float*)d_in[18];
    const float* linW   = (const float*)d_in[19];
    const float* linb   = (const float*)d_in[20];
    float* out = (float*)d_out;
    // bias1/bias2 (d_in[7], d_in[13]) fold out of BN exactly (mean shift)

    const int N = in_sizes[0] / 128;
    const int E = in_sizes[1] / 2;

    void* p;
    cudaGetSymbolAddress(&p, g_count); cudaMemsetAsync(p, 0, (size_t)N * sizeof(int));
    cudaGetSymbolAddress(&p, g_total); cudaMemsetAsync(p, 0, sizeof(int));
    cudaGetSymbolAddress(&p, g_sum1);  cudaMemsetAsync(p, 0, 128 * sizeof(double));
    cudaGetSymbolAddress(&p, g_sq1);   cudaMemsetAsync(p, 0, 128 * sizeof(double));
    cudaGetSymbolAddress(&p, g_sum2);  cudaMemsetAsync(p, 0, 32 * sizeof(double));
    cudaGetSymbolAddress(&p, g_sq2);   cudaMemsetAsync(p, 0, 32 * sizeof(double));

    __half *d_xl1h, *d_xl2h;
    float *d_xr1, *d_res, *d_xr2, *d_agg1, *d_agg2;
    float *d_scale1, *d_shift1, *d_scale2, *d_shift2;
    double *d_sum1, *d_sq1, *d_sum2, *d_sq2;
    cudaGetSymbolAddress((void**)&d_xl1h, g_xl1h);
    cudaGetSymbolAddress((void**)&d_xr1, g_xr1);
    cudaGetSymbolAddress((void**)&d_res, g_res);
    cudaGetSymbolAddress((void**)&d_xl2h, g_xl2h);
    cudaGetSymbolAddress((void**)&d_xr2, g_xr2);
    cudaGetSymbolAddress((void**)&d_agg1, g_agg1);
    cudaGetSymbolAddress((void**)&d_agg2, g_agg2);
    cudaGetSymbolAddress((void**)&d_scale1, g_scale1);
    cudaGetSymbolAddress((void**)&d_shift1, g_shift1);
    cudaGetSymbolAddress((void**)&d_scale2, g_scale2);
    cudaGetSymbolAddress((void**)&d_shift2, g_shift2);
    cudaGetSymbolAddress((void**)&d_sum1, g_sum1);
    cudaGetSymbolAddress((void**)&d_sq1, g_sq1);
    cudaGetSymbolAddress((void**)&d_sum2, g_sum2);
    cudaGetSymbolAddress((void**)&d_sq2, g_sq2);

    const int rowBlocks = (N + 63) / 64;
    const int nodeWarpBlocks = (N * 32 + 255) / 256;

    // ---- CSR build: 3 kernels ----
    csr_hist<<<(E + 255) / 256, 256>>>(ei, E);          // launch 0
    csr_alloc<<<(N + 255) / 256, 256>>>(N);             // launch 1
    csr_scatter<<<(E + 255) / 256, 256>>>(ei, E);       // launch 2

    // conv1 transforms + residual (launch 3 — profiled by ncu)
    transform_kernel<<<dim3(rowBlocks, 5), 256>>>(
        x, N, Wl1, Wr1, skipW, 128, 128, 32,
        bl1, br1, nullptr,
        d_xl1h, d_xr1, d_res, 128, 128, 32,
        nullptr, nullptr);

    agg_conv1<<<nodeWarpBlocks, 256>>>(N, att1);

    bn_stats<128><<<256, 256>>>(d_agg1, N, d_sum1, d_sq1);
    bn_prep<<<1, 128>>>(d_sum1, d_sq1, N, 128, bn1_g, bn1_b, d_scale1, d_shift1);

    // conv2 transforms reading agg1 with on-the-fly BN + ELU
    transform_kernel<<<dim3(rowBlocks, 1), 256>>>(
        d_agg1, N, Wl2, Wr2, nullptr, 32, 32, 0,
        bl2, br2, nullptr,
        d_xl2h, d_xr2, nullptr, 32, 32, 0,
        d_scale1, d_shift1);

    agg_conv2<<<nodeWarpBlocks, 256>>>(N, att2);

    bn_stats<32><<<256, 256>>>(d_agg2, N, d_sum2, d_sq2);
    bn_prep<<<1, 32>>>(d_sum2, d_sq2, N, 32, bn2_g, bn2_b, d_scale2, d_shift2);

    finalize_kernel<<<nodeWarpBlocks, 256>>>(linW, linb, out, N);
}

// round 12
// speedup vs baseline: 1.7338x; 1.0602x over previous
#include <cuda_runtime.h>
#include <cuda_fp16.h>
#include <math.h>

#define MAXN 50000
#define MAXE 800000

// ---------------- scratch (device globals; no allocation allowed) ----------------
__device__ __half g_xl1h[MAXN * 128];
__device__ float g_xr1[MAXN * 128];
__device__ float g_res[MAXN * 32];
__device__ float g_agg1[MAXN * 128];   // normalized conv1 output (pre-bias)
__device__ __half g_xl2h[MAXN * 32];
__device__ float g_xr2[MAXN * 32];
__device__ float g_agg2[MAXN * 32];    // normalized conv2 output (pre-bias)
__device__ double g_sum1[128], g_sq1[128];
__device__ double g_sum2[32], g_sq2[32];
__device__ float g_scale1[128], g_shift1[128];
__device__ float g_scale2[32], g_shift2[32];
// CSR-by-destination (real edges only; self-loops handled inline)
__device__ int g_count[MAXN];
__device__ int g_off[MAXN];
__device__ int g_cursor[MAXN];
__device__ int g_total;
__device__ int g_csr[MAXE];

// ---------------- CSR build ----------------
__global__ void csr_hist(const int* __restrict__ ei, int E) {
    int e = blockIdx.x * blockDim.x + threadIdx.x;
    if (e < E) atomicAdd(&g_count[ei[E + e]], 1);
}

// warp-aggregated offset allocation: contiguous slot range per node, order arbitrary
__global__ void csr_alloc(int N) {
    int i = blockIdx.x * blockDim.x + threadIdx.x;
    int lane = threadIdx.x & 31;
    int c = (i < N) ? g_count[i] : 0;
    int pre = c;
    #pragma unroll
    for (int o = 1; o < 32; o <<= 1) {
        int t = __shfl_up_sync(0xffffffffu, pre, o);
        if (lane >= o) pre += t;
    }
    int wsum = __shfl_sync(0xffffffffu, pre, 31);
    int base = 0;
    if (lane == 31) base = atomicAdd(&g_total, wsum);
    base = __shfl_sync(0xffffffffu, base, 31);
    if (i < N) {
        int off = base + pre - c;
        g_off[i] = off;
        g_cursor[i] = off;
    }
}

__global__ void csr_scatter(const int* __restrict__ ei, int E) {
    int e = blockIdx.x * blockDim.x + threadIdx.x;
    if (e >= E) return;
    int s = ei[e], d = ei[E + e];
    int pos = atomicAdd(&g_cursor[d], 1);
    g_csr[pos] = s;
}

// ---------------- fused dense transform: out = X @ W^T (+bias), K=128 ----------------
// Xs row-major [r][k] (STS.128 conflict-free; compute loads float4 over k, broadcast).
// WsT k-major [k][f] with XOR swizzle on 16B granules: phys_g = g ^ ((k>>2)&15)
// (stores 2-way max; compute LDS.128 is a permutation within 256B => conflict-free).
// o0 written as HALF (o0h); o1/o2 as float. Optional input transform
// (nscale/nshift): v -> elu(v*scale + shift), used for conv2 reading agg1.
__global__ void transform_kernel(
    const float* __restrict__ X, int n,
    const float* __restrict__ W0, const float* __restrict__ W1, const float* __restrict__ W2,
    int F0, int F1, int F2,
    const float* __restrict__ b0, const float* __restrict__ b1, const float* __restrict__ b2,
    __half* __restrict__ o0h, float* __restrict__ o1, float* __restrict__ o2,
    int ld0, int ld1, int ld2,
    const float* __restrict__ nscale,
    const float* __restrict__ nshift)
{
    __shared__ float Xs[64][68];    // [row][k]
    __shared__ float WsT[64][68];   // [k][feat], granule-swizzled
    const int rb = blockIdx.x * 64;
    const int fb = blockIdx.y * 64;
    const int tid = threadIdx.x;
    const int Ft = F0 + F1 + F2;

    const int tx = tid & 15, ty = tid >> 4;
    float acc[4][4];
    #pragma unroll
    for (int i = 0; i < 4; i++)
        #pragma unroll
        for (int j = 0; j < 4; j++) acc[i][j] = 0.f;

    for (int kk = 0; kk < 128; kk += 64) {
        // X tile: row-major, single STS.128 per float4 (conflict-free)
        #pragma unroll
        for (int it = 0; it < 4; it++) {
            int idx = it * 256 + tid;
            int r = idx >> 4;            // 0..63
            int kc = (idx & 15) << 2;    // 0..60
            float4 v = make_float4(0.f, 0.f, 0.f, 0.f);
            int row = rb + r;
            if (row < n) {
                int c = kk + kc;
                v = *(const float4*)(X + (size_t)row * 128 + c);
                if (nscale) {
                    float4 sc = *(const float4*)(nscale + c);
                    float4 sh = *(const float4*)(nshift + c);
                    float a0 = v.x * sc.x + sh.x;
                    float a1 = v.y * sc.y + sh.y;
                    float a2 = v.z * sc.z + sh.z;
                    float a3 = v.w * sc.w + sh.w;
                    v.x = a0 > 0.f ? a0 : expm1f(a0);
                    v.y = a1 > 0.f ? a1 : expm1f(a1);
                    v.z = a2 > 0.f ? a2 : expm1f(a2);
                    v.w = a3 > 0.f ? a3 : expm1f(a3);
                }
            }
            *(float4*)&Xs[r][kc] = v;
        }
        // W tile: k-major with granule swizzle (stores <= 2-way conflicted)
        #pragma unroll
        for (int it = 0; it < 4; it++) {
            int idx = it * 256 + tid;
            int f = idx >> 4;
            int kc = (idx & 15) << 2;
            int gf = fb + f;
            float4 v = make_float4(0.f, 0.f, 0.f, 0.f);
            const float* Wp = nullptr;
            int lf = gf;
            if (gf < F0) { Wp = W0; }
            else if (gf < F0 + F1) { Wp = W1; lf = gf - F0; }
            else if (gf < Ft) { Wp = W2; lf = gf - F0 - F1; }
            if (Wp) v = *(const float4*)(Wp + (size_t)lf * 128 + kk + kc);
            int g0 = f >> 2, c0 = f & 3;
            float vv[4] = {v.x, v.y, v.z, v.w};
            #pragma unroll
            for (int j = 0; j < 4; j++) {
                int k = kc + j;
                int pg = g0 ^ ((k >> 2) & 15);
                WsT[k][pg * 4 + c0] = vv[j];
            }
        }
        __syncthreads();

        // compute: 4 k per iteration
        #pragma unroll 4
        for (int k4 = 0; k4 < 64; k4 += 4) {
            float4 a[4];
            #pragma unroll
            for (int i = 0; i < 4; i++)
                a[i] = *(const float4*)&Xs[ty * 4 + i][k4];
            #pragma unroll
            for (int q = 0; q < 4; q++) {
                int k = k4 + q;
                int pg = tx ^ ((k >> 2) & 15);
                float4 b4 = *(const float4*)&WsT[k][pg * 4];
                float av[4] = {q == 0 ? a[0].x : q == 1 ? a[0].y : q == 2 ? a[0].z : a[0].w,
                               q == 0 ? a[1].x : q == 1 ? a[1].y : q == 2 ? a[1].z : a[1].w,
                               q == 0 ? a[2].x : q == 1 ? a[2].y : q == 2 ? a[2].z : a[2].w,
                               q == 0 ? a[3].x : q == 1 ? a[3].y : q == 2 ? a[3].z : a[3].w};
                #pragma unroll
                for (int i = 0; i < 4; i++) {
                    acc[i][0] += av[i] * b4.x;
                    acc[i][1] += av[i] * b4.y;
                    acc[i][2] += av[i] * b4.z;
                    acc[i][3] += av[i] * b4.w;
                }
            }
        }
        __syncthreads();
    }

    const int gfb = fb + tx * 4;   // 4 consecutive features; Ft multiple of 4 => no straddle
    if (gfb < Ft) {
        #pragma unroll
        for (int i = 0; i < 4; i++) {
            int row = rb + ty * 4 + i;
            if (row >= n) break;
            if (gfb < F0) {
                float a0 = acc[i][0] + (b0 ? b0[gfb + 0] : 0.f);
                float a1 = acc[i][1] + (b0 ? b0[gfb + 1] : 0.f);
                float a2 = acc[i][2] + (b0 ? b0[gfb + 2] : 0.f);
                float a3 = acc[i][3] + (b0 ? b0[gfb + 3] : 0.f);
                __half2 p0 = __floats2half2_rn(a0, a1);
                __half2 p1 = __floats2half2_rn(a2, a3);
                uint2 u;
                u.x = *reinterpret_cast<unsigned*>(&p0);
                u.y = *reinterpret_cast<unsigned*>(&p1);
                *(uint2*)(o0h + (size_t)row * ld0 + gfb) = u;
            } else if (gfb < F0 + F1) {
                int lf = gfb - F0;
                #pragma unroll
                for (int j = 0; j < 4; j++)
                    o1[(size_t)row * ld1 + lf + j] = acc[i][j] + (b1 ? b1[lf + j] : 0.f);
            } else {
                int lf = gfb - F0 - F1;
                #pragma unroll
                for (int j = 0; j < 4; j++)
                    o2[(size_t)row * ld2 + lf + j] = acc[i][j] + (b2 ? b2[lf + j] : 0.f);
            }
        }
    }
}

// ---------------- conv1 edge term ----------------
__device__ __forceinline__ void term1(
    uint2 u, const float4& xr, const float4& at, float4& acc, float& den)
{
    float2 f0 = __half22float2(*reinterpret_cast<__half2*>(&u.x));
    float2 f1 = __half22float2(*reinterpret_cast<__half2*>(&u.y));
    float m0 = f0.x + xr.x, m1 = f0.y + xr.y, m2 = f1.x + xr.z, m3 = f1.y + xr.w;
    float l = (m0 > 0.f ? m0 : 0.2f * m0) * at.x
            + (m1 > 0.f ? m1 : 0.2f * m1) * at.y
            + (m2 > 0.f ? m2 : 0.2f * m2) * at.z
            + (m3 > 0.f ? m3 : 0.2f * m3) * at.w;
    l += __shfl_xor_sync(0xffffffffu, l, 1);
    l += __shfl_xor_sync(0xffffffffu, l, 2);
    l += __shfl_xor_sync(0xffffffffu, l, 4);
    float a = __expf(l);
    acc.x += a * f0.x; acc.y += a * f0.y; acc.z += a * f1.x; acc.w += a * f1.y;
    den += a;
}

// ---------------- conv1 aggregation: warp per node, 1-deep software pipeline ----------------
__global__ void agg_conv1(int N, const float* __restrict__ att)
{
    int w = (blockIdx.x * blockDim.x + threadIdx.x) >> 5;
    int lane = threadIdx.x & 31;
    if (w >= N) return;
    int beg = g_off[w], end = beg + g_count[w];

    float4 xr = *(const float4*)(g_xr1 + (size_t)w * 128 + lane * 4);
    float4 at = *(const float4*)(att + lane * 4);
    float4 acc = make_float4(0.f, 0.f, 0.f, 0.f);
    float den = 0.f;

    uint2 u_next = make_uint2(0u, 0u);
    if (beg < end) {
        int s0 = g_csr[beg];
        u_next = *(const uint2*)(g_xl1h + (size_t)s0 * 128 + lane * 4);
    }
    {
        uint2 u = *(const uint2*)(g_xl1h + (size_t)w * 128 + lane * 4);
        term1(u, xr, at, acc, den);   // implicit self-loop
    }
    for (int j = beg; j < end; j++) {
        uint2 u = u_next;
        if (j + 1 < end) {
            int sn = g_csr[j + 1];
            u_next = *(const uint2*)(g_xl1h + (size_t)sn * 128 + lane * 4);
        }
        term1(u, xr, at, acc, den);
    }
    float inv = __fdividef(1.f, den + 1e-16f);
    acc.x *= inv; acc.y *= inv; acc.z *= inv; acc.w *= inv;
    *(float4*)(g_agg1 + (size_t)w * 128 + lane * 4) = acc;
}

// ---------------- conv2 aggregation: warp per node, 4 edges per iteration ----------------
__global__ void agg_conv2(int N, const float* __restrict__ att)
{
    int w = (blockIdx.x * blockDim.x + threadIdx.x) >> 5;
    int lane = threadIdx.x & 31;
    if (w >= N) return;
    int beg = g_off[w];
    int T = g_count[w] + 1;
    int grp = lane >> 3, sl = lane & 7;

    float4 xr = *(const float4*)(g_xr2 + (size_t)w * 32 + sl * 4);
    float4 at = *(const float4*)(att + sl * 4);
    float4 acc = make_float4(0.f, 0.f, 0.f, 0.f);
    float den = 0.f;

    for (int t0 = 0; t0 < T; t0 += 4) {
        int t = t0 + grp;
        bool valid = t < T;
        int s = w;
        if (valid && t > 0) s = g_csr[beg + t - 1];
        uint2 u = *(const uint2*)(g_xl2h + (size_t)s * 32 + sl * 4);
        float2 f0 = __half22float2(*reinterpret_cast<__half2*>(&u.x));
        float2 f1 = __half22float2(*reinterpret_cast<__half2*>(&u.y));
        float m0 = f0.x + xr.x, m1 = f0.y + xr.y, m2 = f1.x + xr.z, m3 = f1.y + xr.w;
        float l = (m0 > 0.f ? m0 : 0.2f * m0) * at.x
                + (m1 > 0.f ? m1 : 0.2f * m1) * at.y
                + (m2 > 0.f ? m2 : 0.2f * m2) * at.z
                + (m3 > 0.f ? m3 : 0.2f * m3) * at.w;
        l += __shfl_xor_sync(0xffffffffu, l, 1);
        l += __shfl_xor_sync(0xffffffffu, l, 2);
        l += __shfl_xor_sync(0xffffffffu, l, 4);
        float a = valid ? __expf(l) : 0.f;
        acc.x += a * f0.x; acc.y += a * f0.y; acc.z += a * f1.x; acc.w += a * f1.y;
        den += a;
    }
    #pragma unroll
    for (int o = 8; o <= 16; o <<= 1) {
        acc.x += __shfl_xor_sync(0xffffffffu, acc.x, o);
        acc.y += __shfl_xor_sync(0xffffffffu, acc.y, o);
        acc.z += __shfl_xor_sync(0xffffffffu, acc.z, o);
        acc.w += __shfl_xor_sync(0xffffffffu, acc.w, o);
        den   += __shfl_xor_sync(0xffffffffu, den, o);
    }
    if (lane < 8) {
        float inv = __fdividef(1.f, den + 1e-16f);
        acc.x *= inv; acc.y *= inv; acc.z *= inv; acc.w *= inv;
        *(float4*)(g_agg2 + (size_t)w * 32 + sl * 4) = acc;
    }
}

// ---------------- batch-norm statistics over raw normalized agg (no bias) ----------------
template <int C>
__global__ void bn_stats(const float* __restrict__ h, int n,
                         double* __restrict__ sum, double* __restrict__ sq)
{
    const int Q = C / 4;
    int tid = threadIdx.x;
    float s0 = 0.f, s1 = 0.f, s2v = 0.f, s3 = 0.f;
    float t0 = 0.f, t1 = 0.f, t2 = 0.f, t3 = 0.f;
    size_t total4 = (size_t)n * Q;
    const float4* h4 = (const float4*)h;
    for (size_t j = (size_t)blockIdx.x * blockDim.x + tid; j < total4;
         j += (size_t)gridDim.x * blockDim.x) {
        float4 v = h4[j];
        s0 += v.x; t0 += v.x * v.x;
        s1 += v.y; t1 += v.y * v.y;
        s2v += v.z; t2 += v.z * v.z;
        s3 += v.w; t3 += v.w * v.w;
    }
    __shared__ float red[8][256];
    red[0][tid] = s0; red[1][tid] = s1; red[2][tid] = s2v; red[3][tid] = s3;
    red[4][tid] = t0; red[5][tid] = t1; red[6][tid] = t2; red[7][tid] = t3;
    __syncthreads();
    int q = tid & (Q - 1);
    if (tid < Q) {
        const int G = 256 / Q;
        #pragma unroll
        for (int k = 0; k < 8; k++) {
            float acc = 0.f;
            for (int r = 0; r < G; r++) acc += red[k][q + r * Q];
            if (k < 4) atomicAdd(&sum[q * 4 + k], (double)acc);
            else       atomicAdd(&sq[q * 4 + (k - 4)], (double)acc);
        }
    }
}

// ---------------- BN prep ----------------
// downstream value = agg*scale + shift; scale = g*rsqrt(var+eps), shift = -mu*scale + b
__global__ void bn_prep(const double* __restrict__ sum, const double* __restrict__ sq,
                        int n, int C,
                        const float* __restrict__ g, const float* __restrict__ b,
                        float* __restrict__ scale, float* __restrict__ shift)
{
    int c = threadIdx.x;
    if (c >= C) return;
    double mu = sum[c] / n;
    double var = sq[c] / n - mu * mu;
    float istd = rsqrtf((float)var + 1e-5f);
    float sc = istd * g[c];
    scale[c] = sc;
    shift[c] = -(float)mu * sc + b[c];
}

// ---------------- final: BN2 + residual + ELU + [N,32]@[32,2] head ----------------
__global__ void finalize_kernel(const float* __restrict__ linW, const float* __restrict__ linb,
                                float* __restrict__ out, int n)
{
    int gw = (blockIdx.x * blockDim.x + threadIdx.x) >> 5;
    int lane = threadIdx.x & 31;
    if (gw >= n) return;
    float v = g_agg2[(size_t)gw * 32 + lane] * g_scale2[lane] + g_shift2[lane]
            + g_res[(size_t)gw * 32 + lane];
    v = v > 0.f ? v : expm1f(v);
    float o0 = v * linW[lane];
    float o1 = v * linW[32 + lane];
    #pragma unroll
    for (int o = 16; o > 0; o >>= 1) {
        o0 += __shfl_xor_sync(0xffffffffu, o0, o);
        o1 += __shfl_xor_sync(0xffffffffu, o1, o);
    }
    if (lane == 0) {
        out[(size_t)gw * 2] = o0 + linb[0];
        out[(size_t)gw * 2 + 1] = o1 + linb[1];
    }
}

// ---------------- host launcher ----------------
extern "C" void kernel_launch(void* const* d_in, const int* in_sizes, int n_in,
                              void* d_out, int out_size)
{
    const float* x      = (const float*)d_in[0];
    const int*   ei     = (const int*)d_in[1];
    const float* Wl1    = (const float*)d_in[2];
    const float* bl1    = (const float*)d_in[3];
    const float* Wr1    = (const float*)d_in[4];
    const float* br1    = (const float*)d_in[5];
    const float* att1   = (const float*)d_in[6];
    const float* Wl2    = (const float*)d_in[8];
    const float* bl2    = (const float*)d_in[9];
    const float* Wr2    = (const float*)d_in[10];
    const float* br2    = (const float*)d_in[11];
    const float* att2   = (const float*)d_in[12];
    const float* bn1_g  = (const float*)d_in[14];
    const float* bn1_b  = (const float*)d_in[15];
    const float* bn2_g  = (const float*)d_in[16];
    const float* bn2_b  = (const float*)d_in[17];
    const float* skipW  = (const float*)d_in[18];
    const float* linW   = (const float*)d_in[19];
    const float* linb   = (const float*)d_in[20];
    float* out = (float*)d_out;
    // bias1/bias2 (d_in[7], d_in[13]) fold out of BN exactly (mean shift)

    const int N = in_sizes[0] / 128;
    const int E = in_sizes[1] / 2;

    void* p;
    cudaGetSymbolAddress(&p, g_count); cudaMemsetAsync(p, 0, (size_t)N * sizeof(int));
    cudaGetSymbolAddress(&p, g_total); cudaMemsetAsync(p, 0, sizeof(int));
    cudaGetSymbolAddress(&p, g_sum1);  cudaMemsetAsync(p, 0, 128 * sizeof(double));
    cudaGetSymbolAddress(&p, g_sq1);   cudaMemsetAsync(p, 0, 128 * sizeof(double));
    cudaGetSymbolAddress(&p, g_sum2);  cudaMemsetAsync(p, 0, 32 * sizeof(double));
    cudaGetSymbolAddress(&p, g_sq2);   cudaMemsetAsync(p, 0, 32 * sizeof(double));

    __half *d_xl1h, *d_xl2h;
    float *d_xr1, *d_res, *d_xr2, *d_agg1, *d_agg2;
    float *d_scale1, *d_shift1, *d_scale2, *d_shift2;
    double *d_sum1, *d_sq1, *d_sum2, *d_sq2;
    cudaGetSymbolAddress((void**)&d_xl1h, g_xl1h);
    cudaGetSymbolAddress((void**)&d_xr1, g_xr1);
    cudaGetSymbolAddress((void**)&d_res, g_res);
    cudaGetSymbolAddress((void**)&d_xl2h, g_xl2h);
    cudaGetSymbolAddress((void**)&d_xr2, g_xr2);
    cudaGetSymbolAddress((void**)&d_agg1, g_agg1);
    cudaGetSymbolAddress((void**)&d_agg2, g_agg2);
    cudaGetSymbolAddress((void**)&d_scale1, g_scale1);
    cudaGetSymbolAddress((void**)&d_shift1, g_shift1);
    cudaGetSymbolAddress((void**)&d_scale2, g_scale2);
    cudaGetSymbolAddress((void**)&d_shift2, g_shift2);
    cudaGetSymbolAddress((void**)&d_sum1, g_sum1);
    cudaGetSymbolAddress((void**)&d_sq1, g_sq1);
    cudaGetSymbolAddress((void**)&d_sum2, g_sum2);
    cudaGetSymbolAddress((void**)&d_sq2, g_sq2);

    const int rowBlocks = (N + 63) / 64;
    const int nodeWarpBlocks = (N * 32 + 255) / 256;

    // ---- CSR build: 3 kernels ----
    csr_hist<<<(E + 255) / 256, 256>>>(ei, E);          // launch 0
    csr_alloc<<<(N + 255) / 256, 256>>>(N);             // launch 1
    csr_scatter<<<(E + 255) / 256, 256>>>(ei, E);       // launch 2

    // conv1 transforms + residual (launch 3 — profiled by ncu)
    transform_kernel<<<dim3(rowBlocks, 5), 256>>>(
        x, N, Wl1, Wr1, skipW, 128, 128, 32,
        bl1, br1, nullptr,
        d_xl1h, d_xr1, d_res, 128, 128, 32,
        nullptr, nullptr);

    agg_conv1<<<nodeWarpBlocks, 256>>>(N, att1);

    bn_stats<128><<<256, 256>>>(d_agg1, N, d_sum1, d_sq1);
    bn_prep<<<1, 128>>>(d_sum1, d_sq1, N, 128, bn1_g, bn1_b, d_scale1, d_shift1);

    // conv2 transforms reading agg1 with on-the-fly BN + ELU
    transform_kernel<<<dim3(rowBlocks, 1), 256>>>(
        d_agg1, N, Wl2, Wr2, nullptr, 32, 32, 0,
        bl2, br2, nullptr,
        d_xl2h, d_xr2, nullptr, 32, 32, 0,
        d_scale1, d_shift1);

    agg_conv2<<<nodeWarpBlocks, 256>>>(N, att2);

    bn_stats<32><<<256, 256>>>(d_agg2, N, d_sum2, d_sq2);
    bn_prep<<<1, 32>>>(d_sum2, d_sq2, N, 32, bn2_g, bn2_b, d_scale2, d_shift2);

    finalize_kernel<<<nodeWarpBlocks, 256>>>(linW, linb, out, N);
}